// round 1
// baseline (speedup 1.0000x reference)
#include <cuda_runtime.h>
#include <cstdint>

#define NN 113664
#define FF 128
#define EE 909312
#define TT 4
#define BB 1024
#define CC 2
#define NPG 111   // nodes per graph = NN/BB

// ---------------- device scratch (static: no runtime allocation) ----------------
__device__ float g_deg[NN];
__device__ float g_dinv[NN];
__device__ int   g_cnt[NN];
__device__ int   g_rowptr[NN + 1];
__device__ int   g_cursor[NN];
__device__ int   g_col[EE];
__device__ float g_val[EE];
__device__ float g_ax [NN * FF];
__device__ float g_h  [NN * FF];
__device__ float g_out[NN * FF];

// ---------------- math helpers ----------------
__device__ __forceinline__ float tanh_fast(float x) {
    float y;
    asm("tanh.approx.f32 %0, %1;" : "=f"(y) : "f"(x));
    return y;
}
__device__ __forceinline__ float sigmoid_fast(float x) {
    return 0.5f * tanh_fast(0.5f * x) + 0.5f;
}

// ---------------- init: h0 = eye(N,F), out = 0 ----------------
__global__ void k_init_hout() {
    int idx = blockIdx.x * blockDim.x + threadIdx.x;   // float4 index
    if (idx >= NN * FF / 4) return;
    float4 z4 = make_float4(0.f, 0.f, 0.f, 0.f);
    reinterpret_cast<float4*>(g_out)[idx] = z4;
    int base = idx * 4;
    int row = base >> 7;        // /128
    int col = base & 127;
    float4 h4 = z4;
    if (row < FF && row >= col && row <= col + 3) {
        (&h4.x)[row - col] = 1.0f;
    }
    reinterpret_cast<float4*>(g_h)[idx] = h4;
}

// ---------------- per-step CSR build ----------------
__global__ void k_prep() {
    int i = blockIdx.x * blockDim.x + threadIdx.x;
    if (i < NN) { g_deg[i] = 1.0f; g_cnt[i] = 0; }
}

__global__ void k_count(const float* __restrict__ ea, const int* __restrict__ ei) {
    int e = blockIdx.x * blockDim.x + threadIdx.x;
    if (e >= EE) return;
    int d = ei[EE + e];                 // dst
    atomicAdd(&g_deg[d], ea[e]);
    atomicAdd(&g_cnt[d], 1);
}

// single-block scan: 1024 threads, chunk of exactly 111 each (NN = 1024*111)
__global__ void k_scan() {
    __shared__ int sh[1024];
    int tid = threadIdx.x;
    int base = tid * NPG;
    int s = 0;
#pragma unroll 4
    for (int j = 0; j < NPG; j++) s += g_cnt[base + j];
    sh[tid] = s;
    __syncthreads();
#pragma unroll
    for (int off = 1; off < 1024; off <<= 1) {
        int v = (tid >= off) ? sh[tid - off] : 0;
        __syncthreads();
        sh[tid] += v;
        __syncthreads();
    }
    int run = sh[tid] - s;   // exclusive prefix
#pragma unroll 4
    for (int j = 0; j < NPG; j++) {
        int i = base + j;
        g_rowptr[i] = run;
        g_cursor[i] = run;
        run += g_cnt[i];
        g_dinv[i] = rsqrtf(g_deg[i]);
    }
    if (tid == 1023) g_rowptr[NN] = run;
}

__global__ void k_fill(const float* __restrict__ ea, const int* __restrict__ ei) {
    int e = blockIdx.x * blockDim.x + threadIdx.x;
    if (e >= EE) return;
    int s = ei[e];            // src
    int d = ei[EE + e];       // dst
    float nm = g_dinv[s] * ea[e] * g_dinv[d];
    int pos = atomicAdd(&g_cursor[d], 1);
    g_col[pos] = s;
    g_val[pos] = nm;
}

// ---------------- sparse aggregate: ax = (P + D^-1) x, one warp per node ----------------
__global__ void k_agg(const float* __restrict__ x) {
    int gw = (blockIdx.x * blockDim.x + threadIdx.x) >> 5;
    if (gw >= NN) return;
    int lane = threadIdx.x & 31;

    float di = g_dinv[gw];
    float self = di * di;     // 1/deg
    float4 xv = __ldg(reinterpret_cast<const float4*>(x + (size_t)gw * FF) + lane);
    float4 a;
    a.x = self * xv.x; a.y = self * xv.y; a.z = self * xv.z; a.w = self * xv.w;

    int beg = g_rowptr[gw], end = g_rowptr[gw + 1];
    for (int j = beg; j < end; j++) {
        int s = g_col[j];
        float v = g_val[j];
        float4 xs = __ldg(reinterpret_cast<const float4*>(x + (size_t)s * FF) + lane);
        a.x += v * xs.x; a.y += v * xs.y; a.z += v * xs.z; a.w += v * xs.w;
    }
    reinterpret_cast<float4*>(g_ax + (size_t)gw * FF)[lane] = a;
}

// ---------------- fused GRU step ----------------
// TILE_M = 64 rows per CTA, 256 threads: 16 row-groups (4 rows) x 16 col-groups (8 cols)
__device__ __forceinline__ void stageW(float* sW, const float* __restrict__ W, int tid) {
#pragma unroll
    for (int i = 0; i < 16; i++) {
        int idx = tid + i * 256;
        reinterpret_cast<float4*>(sW)[idx] =
            __ldg(reinterpret_cast<const float4*>(W) + idx);
    }
}

// acc += A[row0..row0+3, :] @ sW[:, c0..c0+7]   (A global, row stride FF)
__device__ __forceinline__ void gemm_g(float acc[4][8], const float* __restrict__ A,
                                       int row0, int c0, const float* __restrict__ sW) {
#pragma unroll 2
    for (int k4 = 0; k4 < FF / 4; k4++) {
        float4 av[4];
#pragma unroll
        for (int i = 0; i < 4; i++)
            av[i] = *reinterpret_cast<const float4*>(A + (size_t)(row0 + i) * FF + k4 * 4);
#pragma unroll
        for (int j = 0; j < 4; j++) {
            const float* wr = sW + (k4 * 4 + j) * FF + c0;
            float4 w0 = *reinterpret_cast<const float4*>(wr);
            float4 w1 = *reinterpret_cast<const float4*>(wr + 4);
#pragma unroll
            for (int i = 0; i < 4; i++) {
                float a = (j == 0) ? av[i].x : (j == 1) ? av[i].y : (j == 2) ? av[i].z : av[i].w;
                acc[i][0] += a * w0.x; acc[i][1] += a * w0.y;
                acc[i][2] += a * w0.z; acc[i][3] += a * w0.w;
                acc[i][4] += a * w1.x; acc[i][5] += a * w1.y;
                acc[i][6] += a * w1.z; acc[i][7] += a * w1.w;
            }
        }
    }
}

// acc += sHR[rl0..rl0+3, :] @ sW[:, c0..c0+7]   (sHR shared, row stride 129)
__device__ __forceinline__ void gemm_sh(float acc[4][8], const float* __restrict__ sHR,
                                        int rl0, int c0, const float* __restrict__ sW) {
#pragma unroll 2
    for (int k = 0; k < FF; k++) {
        float a[4];
#pragma unroll
        for (int i = 0; i < 4; i++) a[i] = sHR[(rl0 + i) * 129 + k];
        const float* wr = sW + k * FF + c0;
        float4 w0 = *reinterpret_cast<const float4*>(wr);
        float4 w1 = *reinterpret_cast<const float4*>(wr + 4);
#pragma unroll
        for (int i = 0; i < 4; i++) {
            acc[i][0] += a[i] * w0.x; acc[i][1] += a[i] * w0.y;
            acc[i][2] += a[i] * w0.z; acc[i][3] += a[i] * w0.w;
            acc[i][4] += a[i] * w1.x; acc[i][5] += a[i] * w1.y;
            acc[i][6] += a[i] * w1.z; acc[i][7] += a[i] * w1.w;
        }
    }
}

__global__ void __launch_bounds__(256, 2) k_gru(
    const float* __restrict__ Wzi, const float* __restrict__ bzi,
    const float* __restrict__ Wzh, const float* __restrict__ bzh,
    const float* __restrict__ Wri, const float* __restrict__ bri,
    const float* __restrict__ Wrh, const float* __restrict__ brh,
    const float* __restrict__ Whi, const float* __restrict__ bhi,
    const float* __restrict__ Whh, const float* __restrict__ bhh) {
    extern __shared__ float sm[];
    float* sW  = sm;               // 128*128
    float* sHR = sm + FF * FF;     // 64*129

    const int tid = threadIdx.x;
    const int rg = tid >> 4, cg = tid & 15;
    const int row0 = blockIdx.x * 64 + rg * 4;
    const int rl0 = rg * 4;
    const int c0 = cg * 8;

    float z[4][8];
    float acc[4][8];

    // ---- z = sigmoid(ax@Wzi + bzi + h@Wzh + bzh) ----
#pragma unroll
    for (int i = 0; i < 4; i++)
#pragma unroll
        for (int j = 0; j < 8; j++) acc[i][j] = 0.f;
    stageW(sW, Wzi, tid); __syncthreads();
    gemm_g(acc, g_ax, row0, c0, sW);
    __syncthreads(); stageW(sW, Wzh, tid); __syncthreads();
    gemm_g(acc, g_h, row0, c0, sW);
#pragma unroll
    for (int j = 0; j < 8; j++) {
        float b = __ldg(bzi + c0 + j) + __ldg(bzh + c0 + j);
#pragma unroll
        for (int i = 0; i < 4; i++) z[i][j] = sigmoid_fast(acc[i][j] + b);
    }

    // ---- r = sigmoid(ax@Wri + bri + h@Wrh + brh); hr = r*h ----
#pragma unroll
    for (int i = 0; i < 4; i++)
#pragma unroll
        for (int j = 0; j < 8; j++) acc[i][j] = 0.f;
    __syncthreads(); stageW(sW, Wri, tid); __syncthreads();
    gemm_g(acc, g_ax, row0, c0, sW);
    __syncthreads(); stageW(sW, Wrh, tid); __syncthreads();
    gemm_g(acc, g_h, row0, c0, sW);
#pragma unroll
    for (int j = 0; j < 8; j++) {
        float b = __ldg(bri + c0 + j) + __ldg(brh + c0 + j);
#pragma unroll
        for (int i = 0; i < 4; i++) {
            float rv = sigmoid_fast(acc[i][j] + b);
            float hv = g_h[(size_t)(row0 + i) * FF + c0 + j];
            sHR[(rl0 + i) * 129 + c0 + j] = rv * hv;
        }
    }

    // ---- cand = tanh(ax@Whi + bhi + hr@Whh + bhh) ----
#pragma unroll
    for (int i = 0; i < 4; i++)
#pragma unroll
        for (int j = 0; j < 8; j++) acc[i][j] = 0.f;
    __syncthreads(); stageW(sW, Whi, tid); __syncthreads();
    gemm_g(acc, g_ax, row0, c0, sW);
    __syncthreads(); stageW(sW, Whh, tid); __syncthreads();   // also orders sHR writes->reads
    gemm_sh(acc, sHR, rl0, c0, sW);

    // ---- h_new = (1-z)*hr; out += h_new + z*cand ----
#pragma unroll
    for (int j = 0; j < 8; j++) {
        float b = __ldg(bhi + c0 + j) + __ldg(bhh + c0 + j);
#pragma unroll
        for (int i = 0; i < 4; i++) {
            float cand = tanh_fast(acc[i][j] + b);
            float hrv = sHR[(rl0 + i) * 129 + c0 + j];
            float zv = z[i][j];
            float hn = (1.f - zv) * hrv;
            size_t idx = (size_t)(row0 + i) * FF + c0 + j;
            g_h[idx] = hn;
            g_out[idx] += hn + zv * cand;
        }
    }
}

// ---------------- pooling + classifier ----------------
__global__ void k_pool(const float* __restrict__ Wlin, const float* __restrict__ blin,
                       float* __restrict__ y) {
    int g = blockIdx.x;        // graph
    int f = threadIdx.x;       // feature (128 threads)
    const float* base = g_out + (size_t)g * NPG * FF + f;
    float s = 0.f;
#pragma unroll 4
    for (int n = 0; n < NPG; n++) s += base[(size_t)n * FF];
    s *= (1.0f / (float)NPG);
    float p0 = s * __ldg(Wlin + 2 * f);
    float p1 = s * __ldg(Wlin + 2 * f + 1);
#pragma unroll
    for (int off = 16; off > 0; off >>= 1) {
        p0 += __shfl_down_sync(0xffffffffu, p0, off);
        p1 += __shfl_down_sync(0xffffffffu, p1, off);
    }
    __shared__ float r0s[4], r1s[4];
    int w = f >> 5, lane = f & 31;
    if (lane == 0) { r0s[w] = p0; r1s[w] = p1; }
    __syncthreads();
    if (f == 0) {
        y[2 * g]     = r0s[0] + r0s[1] + r0s[2] + r0s[3] + __ldg(blin);
        y[2 * g + 1] = r1s[0] + r1s[1] + r1s[2] + r1s[3] + __ldg(blin + 1);
    }
}

// ---------------- launch ----------------
extern "C" void kernel_launch(void* const* d_in, const int* in_sizes, int n_in,
                              void* d_out, int out_size) {
    const float* xs = nullptr;
    const float* eas = nullptr;
    const int*   eis = nullptr;
    const float* Wg[6] = {nullptr, nullptr, nullptr, nullptr, nullptr, nullptr};
    const float* bg[6] = {nullptr, nullptr, nullptr, nullptr, nullptr, nullptr};
    const float* Wlin = nullptr;
    const float* blin = nullptr;
    int wi = 0, bi = 0;
    for (int i = 0; i < n_in; i++) {
        long sz = in_sizes[i];
        void* p = d_in[i];
        if (sz == (long)TT * NN * FF)      xs  = (const float*)p;
        else if (sz == (long)TT * EE)      eas = (const float*)p;
        else if (sz == (long)2 * TT * EE)  eis = (const int*)p;
        else if (sz == (long)NN)           { /* batch: contiguous by construction */ }
        else if (sz == (long)FF * FF && wi < 6) Wg[wi++] = (const float*)p;
        else if (sz == (long)FF && bi < 6)      bg[bi++] = (const float*)p;
        else if (sz == (long)FF * CC)      Wlin = (const float*)p;
        else if (sz == (long)CC)           blin = (const float*)p;
    }
    float* y = (float*)d_out;

    const int SMEM_GRU = (FF * FF + 64 * 129) * (int)sizeof(float);  // 98560 B
    cudaFuncSetAttribute(k_gru, cudaFuncAttributeMaxDynamicSharedMemorySize, SMEM_GRU);

    k_init_hout<<<(NN * FF / 4 + 255) / 256, 256>>>();

    for (int t = 0; t < TT; t++) {
        const float* x  = xs  + (size_t)t * NN * FF;
        const float* ea = eas + (size_t)t * EE;
        const int*   ei = eis + (size_t)t * 2 * EE;

        k_prep<<<(NN + 255) / 256, 256>>>();
        k_count<<<(EE + 255) / 256, 256>>>(ea, ei);
        k_scan<<<1, 1024>>>();
        k_fill<<<(EE + 255) / 256, 256>>>(ea, ei);
        k_agg<<<(NN * 32 + 255) / 256, 256>>>(x);
        k_gru<<<NN / 64, 256, SMEM_GRU>>>(Wg[0], bg[0], Wg[1], bg[1],
                                          Wg[2], bg[2], Wg[3], bg[3],
                                          Wg[4], bg[4], Wg[5], bg[5]);
    }
    k_pool<<<BB, 128>>>(Wlin, blin, y);
}

// round 2
// speedup vs baseline: 1.3317x; 1.3317x over previous
#include <cuda_runtime.h>
#include <cstdint>

#define NN 113664
#define FF 128
#define EE 909312
#define TT 4
#define BB 1024
#define CC 2
#define NPG 111        // nodes per graph = NN/BB
#define NBLK 444       // NN / 256

typedef unsigned long long u64;

// ---------------- device scratch (static: no runtime allocation) ----------------
__device__ float g_deg[NN];
__device__ float g_dinv[NN];
__device__ int   g_cnt[NN];
__device__ int   g_rowptr[NN + 1];
__device__ int   g_cursor[NN];
__device__ int   g_bsum[NBLK];
__device__ int   g_boff[NBLK + 1];
__device__ int   g_col[EE];
__device__ float g_val[EE];
__device__ float g_ax [NN * FF];
__device__ float g_h  [NN * FF];
__device__ float g_out[NN * FF];

// ---------------- math helpers ----------------
__device__ __forceinline__ float tanh_fast(float x) {
    float y;
    asm("tanh.approx.f32 %0, %1;" : "=f"(y) : "f"(x));
    return y;
}
__device__ __forceinline__ float sigmoid_fast(float x) {
    return 0.5f * tanh_fast(0.5f * x) + 0.5f;
}

// packed f32x2 helpers (FFMA2 path — only reachable via PTX)
__device__ __forceinline__ u64 pk2(float a, float b) {
    u64 r;
    asm("mov.b64 %0, {%1, %2};" : "=l"(r)
        : "r"(__float_as_uint(a)), "r"(__float_as_uint(b)));
    return r;
}
__device__ __forceinline__ void fma2(u64& d, u64 a, u64 b) {
    asm("fma.rn.f32x2 %0, %1, %2, %0;" : "+l"(d) : "l"(a), "l"(b));
}
__device__ __forceinline__ float2 up2(u64 v) {
    unsigned lo, hi;
    asm("mov.b64 {%0, %1}, %2;" : "=r"(lo), "=r"(hi) : "l"(v));
    return make_float2(__uint_as_float(lo), __uint_as_float(hi));
}

// ---------------- init: h0 = eye(N,F), out = 0 ----------------
__global__ void k_init_hout() {
    int idx = blockIdx.x * blockDim.x + threadIdx.x;   // float4 index
    if (idx >= NN * FF / 4) return;
    float4 z4 = make_float4(0.f, 0.f, 0.f, 0.f);
    reinterpret_cast<float4*>(g_out)[idx] = z4;
    int base = idx * 4;
    int row = base >> 7;        // /128
    int col = base & 127;
    float4 h4 = z4;
    if (row < FF && row >= col && row <= col + 3) {
        (&h4.x)[row - col] = 1.0f;
    }
    reinterpret_cast<float4*>(g_h)[idx] = h4;
}

// ---------------- per-step CSR build ----------------
__global__ void k_prep() {
    int i = blockIdx.x * blockDim.x + threadIdx.x;
    if (i < NN) { g_deg[i] = 1.0f; g_cnt[i] = 0; }
}

__global__ void k_count(const float* __restrict__ ea, const int* __restrict__ ei) {
    int e = blockIdx.x * blockDim.x + threadIdx.x;
    if (e >= EE) return;
    int d = ei[EE + e];                 // dst
    atomicAdd(&g_deg[d], ea[e]);
    atomicAdd(&g_cnt[d], 1);
}

// -------- 3-phase parallel exclusive scan of g_cnt --------
__global__ void k_scan1() {            // 444 blocks x 256: block partial sums
    __shared__ int sh[256];
    int tid = threadIdx.x;
    sh[tid] = g_cnt[blockIdx.x * 256 + tid];
    __syncthreads();
#pragma unroll
    for (int off = 128; off > 0; off >>= 1) {
        if (tid < off) sh[tid] += sh[tid + off];
        __syncthreads();
    }
    if (tid == 0) g_bsum[blockIdx.x] = sh[0];
}

__global__ void k_scan2() {            // 1 block x 512: scan 444 partials
    __shared__ int sh[512];
    int tid = threadIdx.x;
    int v = (tid < NBLK) ? g_bsum[tid] : 0;
    sh[tid] = v;
    __syncthreads();
#pragma unroll
    for (int off = 1; off < 512; off <<= 1) {
        int t = (tid >= off) ? sh[tid - off] : 0;
        __syncthreads();
        sh[tid] += t;
        __syncthreads();
    }
    if (tid < NBLK) g_boff[tid] = sh[tid] - v;    // exclusive
    if (tid == NBLK - 1) g_boff[NBLK] = sh[tid];
}

__global__ void k_scan3() {            // 444 blocks x 256: apply + rowptr/cursor/dinv
    __shared__ int sh[256];
    int tid = threadIdx.x;
    int i = blockIdx.x * 256 + tid;
    int c = g_cnt[i];
    sh[tid] = c;
    __syncthreads();
#pragma unroll
    for (int off = 1; off < 256; off <<= 1) {
        int t = (tid >= off) ? sh[tid - off] : 0;
        __syncthreads();
        sh[tid] += t;
        __syncthreads();
    }
    int excl = sh[tid] - c + g_boff[blockIdx.x];
    g_rowptr[i] = excl;
    g_cursor[i] = excl;
    g_dinv[i] = rsqrtf(g_deg[i]);
    if (i == NN - 1) g_rowptr[NN] = excl + c;
}

__global__ void k_fill(const float* __restrict__ ea, const int* __restrict__ ei) {
    int e = blockIdx.x * blockDim.x + threadIdx.x;
    if (e >= EE) return;
    int s = ei[e];            // src
    int d = ei[EE + e];       // dst
    float nm = g_dinv[s] * ea[e] * g_dinv[d];
    int pos = atomicAdd(&g_cursor[d], 1);
    g_col[pos] = s;
    g_val[pos] = nm;
}

// ---------------- sparse aggregate: ax = (P + D^-1) x, one warp per node ----------------
__global__ void k_agg(const float* __restrict__ x) {
    int gw = (blockIdx.x * blockDim.x + threadIdx.x) >> 5;
    if (gw >= NN) return;
    int lane = threadIdx.x & 31;

    float di = g_dinv[gw];
    float self = di * di;     // 1/deg
    float4 xv = __ldg(reinterpret_cast<const float4*>(x + (size_t)gw * FF) + lane);
    float4 a;
    a.x = self * xv.x; a.y = self * xv.y; a.z = self * xv.z; a.w = self * xv.w;

    int beg = g_rowptr[gw], end = g_rowptr[gw + 1];
    for (int j = beg; j < end; j++) {
        int s = g_col[j];
        float v = g_val[j];
        float4 xs = __ldg(reinterpret_cast<const float4*>(x + (size_t)s * FF) + lane);
        a.x += v * xs.x; a.y += v * xs.y; a.z += v * xs.z; a.w += v * xs.w;
    }
    reinterpret_cast<float4*>(g_ax + (size_t)gw * FF)[lane] = a;
}

// ---------------- fused GRU step (packed f32x2 FMA) ----------------
// TILE_M = 64 rows per CTA, 256 threads: 16 row-groups (4 rows) x 16 col-groups (8 cols)
__device__ __forceinline__ void stageW(float* sW, const float* __restrict__ W, int tid) {
#pragma unroll
    for (int i = 0; i < 16; i++) {
        int idx = tid + i * 256;
        reinterpret_cast<float4*>(sW)[idx] =
            __ldg(reinterpret_cast<const float4*>(W) + idx);
    }
}

// acc2 += A[row0..row0+3, :] @ sW[:, c0..c0+7]   (A global, row stride FF)
__device__ __forceinline__ void gemm_g2(u64 acc2[4][4], const float* __restrict__ A,
                                        int row0, int c0, const float* __restrict__ sW) {
#pragma unroll 2
    for (int k4 = 0; k4 < FF / 4; k4++) {
        float4 av[4];
#pragma unroll
        for (int i = 0; i < 4; i++)
            av[i] = *reinterpret_cast<const float4*>(A + (size_t)(row0 + i) * FF + k4 * 4);
#pragma unroll
        for (int j = 0; j < 4; j++) {
            const ulonglong2* wr =
                reinterpret_cast<const ulonglong2*>(sW + (k4 * 4 + j) * FF + c0);
            ulonglong2 wA = wr[0];
            ulonglong2 wB = wr[1];
#pragma unroll
            for (int i = 0; i < 4; i++) {
                float a = (j == 0) ? av[i].x : (j == 1) ? av[i].y
                        : (j == 2) ? av[i].z : av[i].w;
                u64 ap = pk2(a, a);
                fma2(acc2[i][0], ap, wA.x);
                fma2(acc2[i][1], ap, wA.y);
                fma2(acc2[i][2], ap, wB.x);
                fma2(acc2[i][3], ap, wB.y);
            }
        }
    }
}

// acc2 += sHR[rl0..rl0+3, :] @ sW[:, c0..c0+7]   (sHR shared, row stride 129)
__device__ __forceinline__ void gemm_sh2(u64 acc2[4][4], const float* __restrict__ sHR,
                                         int rl0, int c0, const float* __restrict__ sW) {
#pragma unroll 2
    for (int k = 0; k < FF; k++) {
        const ulonglong2* wr = reinterpret_cast<const ulonglong2*>(sW + k * FF + c0);
        ulonglong2 wA = wr[0];
        ulonglong2 wB = wr[1];
#pragma unroll
        for (int i = 0; i < 4; i++) {
            float a = sHR[(rl0 + i) * 129 + k];
            u64 ap = pk2(a, a);
            fma2(acc2[i][0], ap, wA.x);
            fma2(acc2[i][1], ap, wA.y);
            fma2(acc2[i][2], ap, wB.x);
            fma2(acc2[i][3], ap, wB.y);
        }
    }
}

__device__ __forceinline__ void zero4x4(u64 acc2[4][4]) {
#pragma unroll
    for (int i = 0; i < 4; i++)
#pragma unroll
        for (int j = 0; j < 4; j++) acc2[i][j] = 0ull;
}

__global__ void __launch_bounds__(256, 2) k_gru(
    const float* __restrict__ Wzi, const float* __restrict__ bzi,
    const float* __restrict__ Wzh, const float* __restrict__ bzh,
    const float* __restrict__ Wri, const float* __restrict__ bri,
    const float* __restrict__ Wrh, const float* __restrict__ brh,
    const float* __restrict__ Whi, const float* __restrict__ bhi,
    const float* __restrict__ Whh, const float* __restrict__ bhh) {
    extern __shared__ float sm[];
    float* sW  = sm;               // 128*128
    float* sHR = sm + FF * FF;     // 64*129

    const int tid = threadIdx.x;
    const int rg = tid >> 4, cg = tid & 15;
    const int row0 = blockIdx.x * 64 + rg * 4;
    const int rl0 = rg * 4;
    const int c0 = cg * 8;

    float z[4][8];
    u64 acc2[4][4];

    // ---- z = sigmoid(ax@Wzi + bzi + h@Wzh + bzh) ----
    zero4x4(acc2);
    stageW(sW, Wzi, tid); __syncthreads();
    gemm_g2(acc2, g_ax, row0, c0, sW);
    __syncthreads(); stageW(sW, Wzh, tid); __syncthreads();
    gemm_g2(acc2, g_h, row0, c0, sW);
#pragma unroll
    for (int i = 0; i < 4; i++)
#pragma unroll
        for (int j2 = 0; j2 < 4; j2++) {
            float2 v = up2(acc2[i][j2]);
            int c = c0 + 2 * j2;
            z[i][2 * j2]     = sigmoid_fast(v.x + __ldg(bzi + c)     + __ldg(bzh + c));
            z[i][2 * j2 + 1] = sigmoid_fast(v.y + __ldg(bzi + c + 1) + __ldg(bzh + c + 1));
        }

    // ---- r = sigmoid(ax@Wri + bri + h@Wrh + brh); hr = r*h ----
    zero4x4(acc2);
    __syncthreads(); stageW(sW, Wri, tid); __syncthreads();
    gemm_g2(acc2, g_ax, row0, c0, sW);
    __syncthreads(); stageW(sW, Wrh, tid); __syncthreads();
    gemm_g2(acc2, g_h, row0, c0, sW);
#pragma unroll
    for (int i = 0; i < 4; i++)
#pragma unroll
        for (int j2 = 0; j2 < 4; j2++) {
            float2 v = up2(acc2[i][j2]);
            int c = c0 + 2 * j2;
            float r0 = sigmoid_fast(v.x + __ldg(bri + c)     + __ldg(brh + c));
            float r1 = sigmoid_fast(v.y + __ldg(bri + c + 1) + __ldg(brh + c + 1));
            float h0 = g_h[(size_t)(row0 + i) * FF + c];
            float h1 = g_h[(size_t)(row0 + i) * FF + c + 1];
            sHR[(rl0 + i) * 129 + c]     = r0 * h0;
            sHR[(rl0 + i) * 129 + c + 1] = r1 * h1;
        }

    // ---- cand = tanh(ax@Whi + bhi + hr@Whh + bhh) ----
    zero4x4(acc2);
    __syncthreads(); stageW(sW, Whi, tid); __syncthreads();
    gemm_g2(acc2, g_ax, row0, c0, sW);
    __syncthreads(); stageW(sW, Whh, tid); __syncthreads();   // also orders sHR writes->reads
    gemm_sh2(acc2, sHR, rl0, c0, sW);

    // ---- h_new = (1-z)*hr; out += h_new + z*cand ----
#pragma unroll
    for (int i = 0; i < 4; i++)
#pragma unroll
        for (int j2 = 0; j2 < 4; j2++) {
            float2 v = up2(acc2[i][j2]);
            int c = c0 + 2 * j2;
#pragma unroll
            for (int u = 0; u < 2; u++) {
                float vv = (u == 0) ? v.x : v.y;
                float cand = tanh_fast(vv + __ldg(bhi + c + u) + __ldg(bhh + c + u));
                float hrv = sHR[(rl0 + i) * 129 + c + u];
                float zv = z[i][2 * j2 + u];
                float hn = (1.f - zv) * hrv;
                size_t idx = (size_t)(row0 + i) * FF + c + u;
                g_h[idx] = hn;
                g_out[idx] += hn + zv * cand;
            }
        }
}

// ---------------- pooling + classifier ----------------
__global__ void k_pool(const float* __restrict__ Wlin, const float* __restrict__ blin,
                       float* __restrict__ y) {
    int g = blockIdx.x;        // graph
    int f = threadIdx.x;       // feature (128 threads)
    const float* base = g_out + (size_t)g * NPG * FF + f;
    float s = 0.f;
#pragma unroll 4
    for (int n = 0; n < NPG; n++) s += base[(size_t)n * FF];
    s *= (1.0f / (float)NPG);
    float p0 = s * __ldg(Wlin + 2 * f);
    float p1 = s * __ldg(Wlin + 2 * f + 1);
#pragma unroll
    for (int off = 16; off > 0; off >>= 1) {
        p0 += __shfl_down_sync(0xffffffffu, p0, off);
        p1 += __shfl_down_sync(0xffffffffu, p1, off);
    }
    __shared__ float r0s[4], r1s[4];
    int w = f >> 5, lane = f & 31;
    if (lane == 0) { r0s[w] = p0; r1s[w] = p1; }
    __syncthreads();
    if (f == 0) {
        y[2 * g]     = r0s[0] + r0s[1] + r0s[2] + r0s[3] + __ldg(blin);
        y[2 * g + 1] = r1s[0] + r1s[1] + r1s[2] + r1s[3] + __ldg(blin + 1);
    }
}

// ---------------- launch ----------------
extern "C" void kernel_launch(void* const* d_in, const int* in_sizes, int n_in,
                              void* d_out, int out_size) {
    const float* xs = nullptr;
    const float* eas = nullptr;
    const int*   eis = nullptr;
    const float* Wg[6] = {nullptr, nullptr, nullptr, nullptr, nullptr, nullptr};
    const float* bg[6] = {nullptr, nullptr, nullptr, nullptr, nullptr, nullptr};
    const float* Wlin = nullptr;
    const float* blin = nullptr;
    int wi = 0, bi = 0;
    for (int i = 0; i < n_in; i++) {
        long sz = in_sizes[i];
        void* p = d_in[i];
        if (sz == (long)TT * NN * FF)      xs  = (const float*)p;
        else if (sz == (long)TT * EE)      eas = (const float*)p;
        else if (sz == (long)2 * TT * EE)  eis = (const int*)p;
        else if (sz == (long)NN)           { /* batch: contiguous by construction */ }
        else if (sz == (long)FF * FF && wi < 6) Wg[wi++] = (const float*)p;
        else if (sz == (long)FF && bi < 6)      bg[bi++] = (const float*)p;
        else if (sz == (long)FF * CC)      Wlin = (const float*)p;
        else if (sz == (long)CC)           blin = (const float*)p;
    }
    float* y = (float*)d_out;

    const int SMEM_GRU = (FF * FF + 64 * 129) * (int)sizeof(float);  // 98560 B
    cudaFuncSetAttribute(k_gru, cudaFuncAttributeMaxDynamicSharedMemorySize, SMEM_GRU);

    k_init_hout<<<(NN * FF / 4 + 255) / 256, 256>>>();

    for (int t = 0; t < TT; t++) {
        const float* x  = xs  + (size_t)t * NN * FF;
        const float* ea = eas + (size_t)t * EE;
        const int*   ei = eis + (size_t)t * 2 * EE;

        k_prep<<<(NN + 255) / 256, 256>>>();
        k_count<<<(EE + 255) / 256, 256>>>(ea, ei);
        k_scan1<<<NBLK, 256>>>();
        k_scan2<<<1, 512>>>();
        k_scan3<<<NBLK, 256>>>();
        k_fill<<<(EE + 255) / 256, 256>>>(ea, ei);
        k_agg<<<(NN * 32 + 255) / 256, 256>>>(x);
        k_gru<<<NN / 64, 256, SMEM_GRU>>>(Wg[0], bg[0], Wg[1], bg[1],
                                          Wg[2], bg[2], Wg[3], bg[3],
                                          Wg[4], bg[4], Wg[5], bg[5]);
    }
    k_pool<<<BB, 128>>>(Wlin, blin, y);
}

// round 3
// speedup vs baseline: 2.9511x; 2.2160x over previous
#include <cuda_runtime.h>
#include <cstdint>

#define NN 113664
#define FF 128
#define EE 909312
#define TT 4
#define BB 1024
#define CC 2
#define NPG 111        // nodes per graph = NN/BB
#define NBLK 444       // NN / 256

// GEMM tiling
#define KC 32          // K chunk
#define AS_STR 36      // As row stride (floats) -> conflict-free frags
#define BSZ_STR 260    // Bs stride for N=256 kernel
#define BSC_STR 132    // Bs stride for N=128 kernel

// ---------------- device scratch (static: no runtime allocation) ----------------
__device__ float g_deg[NN];
__device__ float g_dinv[NN];
__device__ int   g_cnt[NN];
__device__ int   g_rowptr[NN + 1];
__device__ int   g_cursor[NN];
__device__ int   g_bsum[NBLK];
__device__ int   g_boff[NBLK + 1];
__device__ int   g_col[EE];
__device__ float g_val[EE];
__device__ float g_ax [NN * FF];
__device__ float g_h  [NN * FF];
__device__ float g_hr [NN * FF];
__device__ float g_z  [NN * FF];
__device__ float g_out[NN * FF];
__device__ unsigned g_Wzr[256 * 256];   // packed tf32 bits: [k][n]  n<128:z  n>=128:r
__device__ unsigned g_Whc[256 * 128];   // packed tf32 bits: [k][n]
__device__ float g_bias_zr[256];
__device__ float g_bias_c[128];

// ---------------- math helpers ----------------
__device__ __forceinline__ float tanh_fast(float x) {
    float y;
    asm("tanh.approx.f32 %0, %1;" : "=f"(y) : "f"(x));
    return y;
}
__device__ __forceinline__ float sigmoid_fast(float x) {
    return 0.5f * tanh_fast(0.5f * x) + 0.5f;
}
__device__ __forceinline__ unsigned f2tf(float x) {
    unsigned r;
    asm("cvt.rna.tf32.f32 %0, %1;" : "=r"(r) : "f"(x));
    return r;
}
__device__ __forceinline__ void mma_tf32(float d[4], const unsigned a[4], const unsigned b[2]) {
    asm volatile(
        "mma.sync.aligned.m16n8k8.row.col.f32.tf32.tf32.f32 "
        "{%0,%1,%2,%3}, {%4,%5,%6,%7}, {%8,%9}, {%0,%1,%2,%3};"
        : "+f"(d[0]), "+f"(d[1]), "+f"(d[2]), "+f"(d[3])
        : "r"(a[0]), "r"(a[1]), "r"(a[2]), "r"(a[3]), "r"(b[0]), "r"(b[1]));
}

// ---------------- init: h0 = eye(N,F), out = 0 ----------------
__global__ void k_init_hout() {
    int idx = blockIdx.x * blockDim.x + threadIdx.x;
    if (idx >= NN * FF / 4) return;
    float4 z4 = make_float4(0.f, 0.f, 0.f, 0.f);
    reinterpret_cast<float4*>(g_out)[idx] = z4;
    int base = idx * 4;
    int row = base >> 7;
    int col = base & 127;
    float4 h4 = z4;
    if (row < FF && row >= col && row <= col + 3) {
        (&h4.x)[row - col] = 1.0f;
    }
    reinterpret_cast<float4*>(g_h)[idx] = h4;
}

// ---------------- weight packing (once per launch) ----------------
__global__ void k_pack(const float* __restrict__ Wzi, const float* __restrict__ bzi,
                       const float* __restrict__ Wzh, const float* __restrict__ bzh,
                       const float* __restrict__ Wri, const float* __restrict__ bri,
                       const float* __restrict__ Wrh, const float* __restrict__ brh,
                       const float* __restrict__ Whi, const float* __restrict__ bhi,
                       const float* __restrict__ Whh, const float* __restrict__ bhh) {
    int i = blockIdx.x * blockDim.x + threadIdx.x;
    if (i < 65536) {
        int k = i >> 8, n = i & 255;
        float v;
        if (k < 128) v = (n < 128) ? Wzi[k * 128 + n] : Wri[k * 128 + (n - 128)];
        else         v = (n < 128) ? Wzh[(k - 128) * 128 + n] : Wrh[(k - 128) * 128 + (n - 128)];
        g_Wzr[i] = f2tf(v);
    } else if (i < 65536 + 32768) {
        int j = i - 65536;
        int k = j >> 7, n = j & 127;
        float v = (k < 128) ? Whi[k * 128 + n] : Whh[(k - 128) * 128 + n];
        g_Whc[j] = f2tf(v);
    } else if (i < 65536 + 32768 + 256) {
        int n = i - (65536 + 32768);
        g_bias_zr[n] = (n < 128) ? (bzi[n] + bzh[n]) : (bri[n - 128] + brh[n - 128]);
    } else if (i < 65536 + 32768 + 256 + 128) {
        int n = i - (65536 + 32768 + 256);
        g_bias_c[n] = bhi[n] + bhh[n];
    }
}

// ---------------- per-step CSR build ----------------
__global__ void k_prep() {
    int i = blockIdx.x * blockDim.x + threadIdx.x;
    if (i < NN) { g_deg[i] = 1.0f; g_cnt[i] = 0; }
}

__global__ void k_count(const float* __restrict__ ea, const int* __restrict__ ei) {
    int e = blockIdx.x * blockDim.x + threadIdx.x;
    if (e >= EE) return;
    int d = ei[EE + e];
    atomicAdd(&g_deg[d], ea[e]);
    atomicAdd(&g_cnt[d], 1);
}

__global__ void k_scan1() {
    __shared__ int sh[256];
    int tid = threadIdx.x;
    sh[tid] = g_cnt[blockIdx.x * 256 + tid];
    __syncthreads();
#pragma unroll
    for (int off = 128; off > 0; off >>= 1) {
        if (tid < off) sh[tid] += sh[tid + off];
        __syncthreads();
    }
    if (tid == 0) g_bsum[blockIdx.x] = sh[0];
}

__global__ void k_scan2() {
    __shared__ int sh[512];
    int tid = threadIdx.x;
    int v = (tid < NBLK) ? g_bsum[tid] : 0;
    sh[tid] = v;
    __syncthreads();
#pragma unroll
    for (int off = 1; off < 512; off <<= 1) {
        int t = (tid >= off) ? sh[tid - off] : 0;
        __syncthreads();
        sh[tid] += t;
        __syncthreads();
    }
    if (tid < NBLK) g_boff[tid] = sh[tid] - v;
    if (tid == NBLK - 1) g_boff[NBLK] = sh[tid];
}

__global__ void k_scan3() {
    __shared__ int sh[256];
    int tid = threadIdx.x;
    int i = blockIdx.x * 256 + tid;
    int c = g_cnt[i];
    sh[tid] = c;
    __syncthreads();
#pragma unroll
    for (int off = 1; off < 256; off <<= 1) {
        int t = (tid >= off) ? sh[tid - off] : 0;
        __syncthreads();
        sh[tid] += t;
        __syncthreads();
    }
    int excl = sh[tid] - c + g_boff[blockIdx.x];
    g_rowptr[i] = excl;
    g_cursor[i] = excl;
    g_dinv[i] = rsqrtf(g_deg[i]);
    if (i == NN - 1) g_rowptr[NN] = excl + c;
}

__global__ void k_fill(const float* __restrict__ ea, const int* __restrict__ ei) {
    int e = blockIdx.x * blockDim.x + threadIdx.x;
    if (e >= EE) return;
    int s = ei[e];
    int d = ei[EE + e];
    float nm = g_dinv[s] * ea[e] * g_dinv[d];
    int pos = atomicAdd(&g_cursor[d], 1);
    g_col[pos] = s;
    g_val[pos] = nm;
}

// ---------------- sparse aggregate: ax = (P + D^-1) x ----------------
__global__ void k_agg(const float* __restrict__ x) {
    int gw = (blockIdx.x * blockDim.x + threadIdx.x) >> 5;
    if (gw >= NN) return;
    int lane = threadIdx.x & 31;

    float di = g_dinv[gw];
    float self = di * di;
    float4 xv = __ldg(reinterpret_cast<const float4*>(x + (size_t)gw * FF) + lane);
    float4 a;
    a.x = self * xv.x; a.y = self * xv.y; a.z = self * xv.z; a.w = self * xv.w;

    int beg = g_rowptr[gw], end = g_rowptr[gw + 1];
    for (int j = beg; j < end; j++) {
        int s = g_col[j];
        float v = g_val[j];
        float4 xs = __ldg(reinterpret_cast<const float4*>(x + (size_t)s * FF) + lane);
        a.x += v * xs.x; a.y += v * xs.y; a.z += v * xs.z; a.w += v * xs.w;
    }
    reinterpret_cast<float4*>(g_ax + (size_t)gw * FF)[lane] = a;
}

// ================= GEMM 1: [ax|h] (M x 256) @ Wzr (256 x 256) -> z, hr =================
// BM=64, BN=256, 256 threads = 8 warps as 2x4 (wm in {0,1}, wn in {0..3})
// warp tile 32x64 -> mt=2 m16-tiles, nt=8 n8-tiles
__global__ void __launch_bounds__(256) k_zr() {
    extern __shared__ unsigned sm[];
    unsigned* As = sm;                     // [64][AS_STR]
    unsigned* Bs = sm + 64 * AS_STR;       // [KC][BSZ_STR]

    const int tid = threadIdx.x;
    const int w = tid >> 5, lane = tid & 31;
    const int wm = w & 1, wn = w >> 1;
    const int gid = lane >> 2, tig = lane & 3;
    const int row0 = blockIdx.x * 64;

    float acc[2][8][4];
#pragma unroll
    for (int mt = 0; mt < 2; mt++)
#pragma unroll
        for (int nt = 0; nt < 8; nt++)
#pragma unroll
            for (int q = 0; q < 4; q++) acc[mt][nt][q] = 0.f;

#pragma unroll
    for (int chunk = 0; chunk < 8; chunk++) {
        const float* Ap = ((chunk < 4) ? g_ax : g_h)
                        + (size_t)row0 * FF + (chunk & 3) * KC;
        // stage A: 64x32 floats (512 float4), cvt to tf32
#pragma unroll
        for (int t = 0; t < 2; t++) {
            int i = tid + t * 256;
            int r = i >> 3, j = i & 7;
            float4 v = __ldg(reinterpret_cast<const float4*>(Ap + (size_t)r * FF) + j);
            unsigned* dst = As + r * AS_STR + j * 4;
            dst[0] = f2tf(v.x); dst[1] = f2tf(v.y); dst[2] = f2tf(v.z); dst[3] = f2tf(v.w);
        }
        // stage B: 32x256 tf32 (2048 uint4-quarters -> 2048 uint4/4?) 32*256/4=2048 uint4
        const uint4* Bp = reinterpret_cast<const uint4*>(g_Wzr + (size_t)chunk * KC * 256);
#pragma unroll
        for (int t = 0; t < 8; t++) {
            int i = tid + t * 256;
            int r = i >> 6, j = i & 63;
            uint4 v = Bp[r * 64 + j];
            *reinterpret_cast<uint4*>(Bs + r * BSZ_STR + j * 4) = v;
        }
        __syncthreads();

#pragma unroll
        for (int k8 = 0; k8 < 4; k8++) {
            int kk = k8 * 8;
            unsigned a[2][4];
#pragma unroll
            for (int mt = 0; mt < 2; mt++) {
                int rb = wm * 32 + mt * 16 + gid;
                a[mt][0] = As[rb * AS_STR + kk + tig];
                a[mt][1] = As[(rb + 8) * AS_STR + kk + tig];
                a[mt][2] = As[rb * AS_STR + kk + tig + 4];
                a[mt][3] = As[(rb + 8) * AS_STR + kk + tig + 4];
            }
#pragma unroll
            for (int nt = 0; nt < 8; nt++) {
                unsigned b[2];
                int cb = wn * 64 + nt * 8 + gid;
                b[0] = Bs[(kk + tig) * BSZ_STR + cb];
                b[1] = Bs[(kk + tig + 4) * BSZ_STR + cb];
                mma_tf32(acc[0][nt], a[0], b);
                mma_tf32(acc[1][nt], a[1], b);
            }
        }
        __syncthreads();
    }

    // epilogue: wn 0,1 -> z cols [0,128); wn 2,3 -> r cols [128,256)
#pragma unroll
    for (int mt = 0; mt < 2; mt++) {
#pragma unroll
        for (int nt = 0; nt < 8; nt++) {
            int col = wn * 64 + nt * 8 + 2 * tig;
            int r1 = row0 + wm * 32 + mt * 16 + gid;
            int r2 = r1 + 8;
            float b0 = g_bias_zr[col], b1 = g_bias_zr[col + 1];
            if (wn < 2) {
                int n = col;
                float2 z1 = make_float2(sigmoid_fast(acc[mt][nt][0] + b0),
                                        sigmoid_fast(acc[mt][nt][1] + b1));
                float2 z2 = make_float2(sigmoid_fast(acc[mt][nt][2] + b0),
                                        sigmoid_fast(acc[mt][nt][3] + b1));
                *reinterpret_cast<float2*>(g_z + (size_t)r1 * FF + n) = z1;
                *reinterpret_cast<float2*>(g_z + (size_t)r2 * FF + n) = z2;
            } else {
                int n = col - 128;
                float2 h1 = *reinterpret_cast<const float2*>(g_h + (size_t)r1 * FF + n);
                float2 h2 = *reinterpret_cast<const float2*>(g_h + (size_t)r2 * FF + n);
                float2 o1 = make_float2(sigmoid_fast(acc[mt][nt][0] + b0) * h1.x,
                                        sigmoid_fast(acc[mt][nt][1] + b1) * h1.y);
                float2 o2 = make_float2(sigmoid_fast(acc[mt][nt][2] + b0) * h2.x,
                                        sigmoid_fast(acc[mt][nt][3] + b1) * h2.y);
                *reinterpret_cast<float2*>(g_hr + (size_t)r1 * FF + n) = o1;
                *reinterpret_cast<float2*>(g_hr + (size_t)r2 * FF + n) = o2;
            }
        }
    }
}

// ================= GEMM 2: [ax|hr] (M x 256) @ Whc (256 x 128) -> h, out =================
// BM=64, BN=128, 8 warps 2x4, warp tile 32x32 -> mt=2, nt=4
__global__ void __launch_bounds__(256) k_cand() {
    extern __shared__ unsigned sm[];
    unsigned* As = sm;
    unsigned* Bs = sm + 64 * AS_STR;       // [KC][BSC_STR]

    const int tid = threadIdx.x;
    const int w = tid >> 5, lane = tid & 31;
    const int wm = w & 1, wn = w >> 1;
    const int gid = lane >> 2, tig = lane & 3;
    const int row0 = blockIdx.x * 64;

    float acc[2][4][4];
#pragma unroll
    for (int mt = 0; mt < 2; mt++)
#pragma unroll
        for (int nt = 0; nt < 4; nt++)
#pragma unroll
            for (int q = 0; q < 4; q++) acc[mt][nt][q] = 0.f;

#pragma unroll
    for (int chunk = 0; chunk < 8; chunk++) {
        const float* Ap = ((chunk < 4) ? g_ax : g_hr)
                        + (size_t)row0 * FF + (chunk & 3) * KC;
#pragma unroll
        for (int t = 0; t < 2; t++) {
            int i = tid + t * 256;
            int r = i >> 3, j = i & 7;
            float4 v = __ldg(reinterpret_cast<const float4*>(Ap + (size_t)r * FF) + j);
            unsigned* dst = As + r * AS_STR + j * 4;
            dst[0] = f2tf(v.x); dst[1] = f2tf(v.y); dst[2] = f2tf(v.z); dst[3] = f2tf(v.w);
        }
        const uint4* Bp = reinterpret_cast<const uint4*>(g_Whc + (size_t)chunk * KC * 128);
#pragma unroll
        for (int t = 0; t < 4; t++) {
            int i = tid + t * 256;
            int r = i >> 5, j = i & 31;
            uint4 v = Bp[r * 32 + j];
            *reinterpret_cast<uint4*>(Bs + r * BSC_STR + j * 4) = v;
        }
        __syncthreads();

#pragma unroll
        for (int k8 = 0; k8 < 4; k8++) {
            int kk = k8 * 8;
            unsigned a[2][4];
#pragma unroll
            for (int mt = 0; mt < 2; mt++) {
                int rb = wm * 32 + mt * 16 + gid;
                a[mt][0] = As[rb * AS_STR + kk + tig];
                a[mt][1] = As[(rb + 8) * AS_STR + kk + tig];
                a[mt][2] = As[rb * AS_STR + kk + tig + 4];
                a[mt][3] = As[(rb + 8) * AS_STR + kk + tig + 4];
            }
#pragma unroll
            for (int nt = 0; nt < 4; nt++) {
                unsigned b[2];
                int cb = wn * 32 + nt * 8 + gid;
                b[0] = Bs[(kk + tig) * BSC_STR + cb];
                b[1] = Bs[(kk + tig + 4) * BSC_STR + cb];
                mma_tf32(acc[0][nt], a[0], b);
                mma_tf32(acc[1][nt], a[1], b);
            }
        }
        __syncthreads();
    }

    // epilogue: cand = tanh(acc + bias); hn = (1-z)*hr; h = hn; out += hn + z*cand
#pragma unroll
    for (int mt = 0; mt < 2; mt++) {
#pragma unroll
        for (int nt = 0; nt < 4; nt++) {
            int n = wn * 32 + nt * 8 + 2 * tig;
            float b0 = g_bias_c[n], b1 = g_bias_c[n + 1];
#pragma unroll
            for (int half = 0; half < 2; half++) {
                int row = row0 + wm * 32 + mt * 16 + gid + half * 8;
                float c0 = tanh_fast(acc[mt][nt][half * 2]     + b0);
                float c1 = tanh_fast(acc[mt][nt][half * 2 + 1] + b1);
                size_t idx = (size_t)row * FF + n;
                float2 zv = *reinterpret_cast<const float2*>(g_z + idx);
                float2 hr = *reinterpret_cast<const float2*>(g_hr + idx);
                float2 hn = make_float2((1.f - zv.x) * hr.x, (1.f - zv.y) * hr.y);
                *reinterpret_cast<float2*>(g_h + idx) = hn;
                float2 ov = *reinterpret_cast<float2*>(g_out + idx);
                ov.x += hn.x + zv.x * c0;
                ov.y += hn.y + zv.y * c1;
                *reinterpret_cast<float2*>(g_out + idx) = ov;
            }
        }
    }
}

// ---------------- pooling + classifier ----------------
__global__ void k_pool(const float* __restrict__ Wlin, const float* __restrict__ blin,
                       float* __restrict__ y) {
    int g = blockIdx.x;
    int f = threadIdx.x;
    const float* base = g_out + (size_t)g * NPG * FF + f;
    float s = 0.f;
#pragma unroll 4
    for (int n = 0; n < NPG; n++) s += base[(size_t)n * FF];
    s *= (1.0f / (float)NPG);
    float p0 = s * __ldg(Wlin + 2 * f);
    float p1 = s * __ldg(Wlin + 2 * f + 1);
#pragma unroll
    for (int off = 16; off > 0; off >>= 1) {
        p0 += __shfl_down_sync(0xffffffffu, p0, off);
        p1 += __shfl_down_sync(0xffffffffu, p1, off);
    }
    __shared__ float r0s[4], r1s[4];
    int w = f >> 5, lane = f & 31;
    if (lane == 0) { r0s[w] = p0; r1s[w] = p1; }
    __syncthreads();
    if (f == 0) {
        y[2 * g]     = r0s[0] + r0s[1] + r0s[2] + r0s[3] + __ldg(blin);
        y[2 * g + 1] = r1s[0] + r1s[1] + r1s[2] + r1s[3] + __ldg(blin + 1);
    }
}

// ---------------- launch ----------------
extern "C" void kernel_launch(void* const* d_in, const int* in_sizes, int n_in,
                              void* d_out, int out_size) {
    const float* xs = nullptr;
    const float* eas = nullptr;
    const int*   eis = nullptr;
    const float* Wg[6] = {nullptr, nullptr, nullptr, nullptr, nullptr, nullptr};
    const float* bg[6] = {nullptr, nullptr, nullptr, nullptr, nullptr, nullptr};
    const float* Wlin = nullptr;
    const float* blin = nullptr;
    int wi = 0, bi = 0;
    for (int i = 0; i < n_in; i++) {
        long sz = in_sizes[i];
        void* p = d_in[i];
        if (sz == (long)TT * NN * FF)      xs  = (const float*)p;
        else if (sz == (long)TT * EE)      eas = (const float*)p;
        else if (sz == (long)2 * TT * EE)  eis = (const int*)p;
        else if (sz == (long)NN)           { /* batch: contiguous by construction */ }
        else if (sz == (long)FF * FF && wi < 6) Wg[wi++] = (const float*)p;
        else if (sz == (long)FF && bi < 6)      bg[bi++] = (const float*)p;
        else if (sz == (long)FF * CC)      Wlin = (const float*)p;
        else if (sz == (long)CC)           blin = (const float*)p;
    }
    float* y = (float*)d_out;

    const int SMEM_ZR   = (64 * AS_STR + KC * BSZ_STR) * 4;   // 42496 B
    const int SMEM_CAND = (64 * AS_STR + KC * BSC_STR) * 4;   // 26112 B
    cudaFuncSetAttribute(k_zr,   cudaFuncAttributeMaxDynamicSharedMemorySize, SMEM_ZR);
    cudaFuncSetAttribute(k_cand, cudaFuncAttributeMaxDynamicSharedMemorySize, SMEM_CAND);

    k_init_hout<<<(NN * FF / 4 + 255) / 256, 256>>>();
    k_pack<<<(65536 + 32768 + 256 + 128 + 255) / 256, 256>>>(
        Wg[0], bg[0], Wg[1], bg[1], Wg[2], bg[2],
        Wg[3], bg[3], Wg[4], bg[4], Wg[5], bg[5]);

    for (int t = 0; t < TT; t++) {
        const float* x  = xs  + (size_t)t * NN * FF;
        const float* ea = eas + (size_t)t * EE;
        const int*   ei = eis + (size_t)t * 2 * EE;

        k_prep<<<(NN + 255) / 256, 256>>>();
        k_count<<<(EE + 255) / 256, 256>>>(ea, ei);
        k_scan1<<<NBLK, 256>>>();
        k_scan2<<<1, 512>>>();
        k_scan3<<<NBLK, 256>>>();
        k_fill<<<(EE + 255) / 256, 256>>>(ea, ei);
        k_agg<<<(NN * 32 + 255) / 256, 256>>>(x);
        k_zr<<<NN / 64, 256, SMEM_ZR>>>();
        k_cand<<<NN / 64, 256, SMEM_CAND>>>();
    }
    k_pool<<<BB, 128>>>(Wlin, blin, y);
}

// round 4
// speedup vs baseline: 3.4993x; 1.1858x over previous
#include <cuda_runtime.h>
#include <cstdint>

#define NN 113664
#define FF 128
#define EE 909312
#define TT 4
#define BB 1024
#define CC 2
#define NPG 111        // nodes per graph = NN/BB
#define NBLK 444       // NN / 256

// GEMM tiling
#define KC 32          // K chunk
#define AS_STR 36      // As row stride (floats) -> conflict-free frags
#define BSZ_STR 260    // Bs stride for N=256 phase
#define BSC_STR 132    // Bs stride for N=128 phase
#define HR_STR 132     // z/hr smem stride

// ---------------- device scratch (static: no runtime allocation) ----------------
__device__ float g_deg[NN];
__device__ float g_dinv[NN];
__device__ int   g_cnt[NN];
__device__ int   g_rowptr[NN + 1];
__device__ int   g_cursor[NN];
__device__ int   g_bsum[NBLK];
__device__ int   g_boff[NBLK + 1];
__device__ int   g_col[EE];
__device__ float g_val[EE];
__device__ float g_ax [NN * FF];
__device__ float g_h  [NN * FF];
__device__ float g_out[NN * FF];
__device__ unsigned g_Wzr[256 * 256];   // packed tf32 bits: [k][n]  n<128:z  n>=128:r
__device__ unsigned g_Whc[256 * 128];   // packed tf32 bits: [k][n]
__device__ float g_bias_zr[256];
__device__ float g_bias_c[128];

// ---------------- math helpers ----------------
__device__ __forceinline__ float tanh_fast(float x) {
    float y;
    asm("tanh.approx.f32 %0, %1;" : "=f"(y) : "f"(x));
    return y;
}
__device__ __forceinline__ float sigmoid_fast(float x) {
    return 0.5f * tanh_fast(0.5f * x) + 0.5f;
}
__device__ __forceinline__ unsigned f2tf(float x) {
    unsigned r;
    asm("cvt.rna.tf32.f32 %0, %1;" : "=r"(r) : "f"(x));
    return r;
}
__device__ __forceinline__ void mma_tf32(float d[4], const unsigned a[4], const unsigned b[2]) {
    asm volatile(
        "mma.sync.aligned.m16n8k8.row.col.f32.tf32.tf32.f32 "
        "{%0,%1,%2,%3}, {%4,%5,%6,%7}, {%8,%9}, {%0,%1,%2,%3};"
        : "+f"(d[0]), "+f"(d[1]), "+f"(d[2]), "+f"(d[3])
        : "r"(a[0]), "r"(a[1]), "r"(a[2]), "r"(a[3]), "r"(b[0]), "r"(b[1]));
}

// ---------------- init: h0 = eye(N,F), out = 0 ----------------
__global__ void k_init_hout() {
    int idx = blockIdx.x * blockDim.x + threadIdx.x;
    if (idx >= NN * FF / 4) return;
    float4 z4 = make_float4(0.f, 0.f, 0.f, 0.f);
    reinterpret_cast<float4*>(g_out)[idx] = z4;
    int base = idx * 4;
    int row = base >> 7;
    int col = base & 127;
    float4 h4 = z4;
    if (row < FF && row >= col && row <= col + 3) {
        (&h4.x)[row - col] = 1.0f;
    }
    reinterpret_cast<float4*>(g_h)[idx] = h4;
}

// ---------------- weight packing (once per launch) ----------------
__global__ void k_pack(const float* __restrict__ Wzi, const float* __restrict__ bzi,
                       const float* __restrict__ Wzh, const float* __restrict__ bzh,
                       const float* __restrict__ Wri, const float* __restrict__ bri,
                       const float* __restrict__ Wrh, const float* __restrict__ brh,
                       const float* __restrict__ Whi, const float* __restrict__ bhi,
                       const float* __restrict__ Whh, const float* __restrict__ bhh) {
    int i = blockIdx.x * blockDim.x + threadIdx.x;
    if (i < 65536) {
        int k = i >> 8, n = i & 255;
        float v;
        if (k < 128) v = (n < 128) ? Wzi[k * 128 + n] : Wri[k * 128 + (n - 128)];
        else         v = (n < 128) ? Wzh[(k - 128) * 128 + n] : Wrh[(k - 128) * 128 + (n - 128)];
        g_Wzr[i] = f2tf(v);
    } else if (i < 65536 + 32768) {
        int j = i - 65536;
        int k = j >> 7, n = j & 127;
        float v = (k < 128) ? Whi[k * 128 + n] : Whh[(k - 128) * 128 + n];
        g_Whc[j] = f2tf(v);
    } else if (i < 65536 + 32768 + 256) {
        int n = i - (65536 + 32768);
        g_bias_zr[n] = (n < 128) ? (bzi[n] + bzh[n]) : (bri[n - 128] + brh[n - 128]);
    } else if (i < 65536 + 32768 + 256 + 128) {
        int n = i - (65536 + 32768 + 256);
        g_bias_c[n] = bhi[n] + bhh[n];
    }
}

// ---------------- per-step CSR build ----------------
__global__ void k_prep() {
    int i = blockIdx.x * blockDim.x + threadIdx.x;
    if (i < NN) { g_deg[i] = 1.0f; g_cnt[i] = 0; }
}

__global__ void k_count(const float* __restrict__ ea, const int* __restrict__ ei) {
    int e = blockIdx.x * blockDim.x + threadIdx.x;
    if (e >= EE) return;
    int d = ei[EE + e];
    atomicAdd(&g_deg[d], ea[e]);
    atomicAdd(&g_cnt[d], 1);
}

__global__ void k_scan1() {
    __shared__ int sh[256];
    int tid = threadIdx.x;
    sh[tid] = g_cnt[blockIdx.x * 256 + tid];
    __syncthreads();
#pragma unroll
    for (int off = 128; off > 0; off >>= 1) {
        if (tid < off) sh[tid] += sh[tid + off];
        __syncthreads();
    }
    if (tid == 0) g_bsum[blockIdx.x] = sh[0];
}

__global__ void k_scan2() {
    __shared__ int sh[512];
    int tid = threadIdx.x;
    int v = (tid < NBLK) ? g_bsum[tid] : 0;
    sh[tid] = v;
    __syncthreads();
#pragma unroll
    for (int off = 1; off < 512; off <<= 1) {
        int t = (tid >= off) ? sh[tid - off] : 0;
        __syncthreads();
        sh[tid] += t;
        __syncthreads();
    }
    if (tid < NBLK) g_boff[tid] = sh[tid] - v;
    if (tid == NBLK - 1) g_boff[NBLK] = sh[tid];
}

__global__ void k_scan3() {
    __shared__ int sh[256];
    int tid = threadIdx.x;
    int i = blockIdx.x * 256 + tid;
    int c = g_cnt[i];
    sh[tid] = c;
    __syncthreads();
#pragma unroll
    for (int off = 1; off < 256; off <<= 1) {
        int t = (tid >= off) ? sh[tid - off] : 0;
        __syncthreads();
        sh[tid] += t;
        __syncthreads();
    }
    int excl = sh[tid] - c + g_boff[blockIdx.x];
    g_rowptr[i] = excl;
    g_cursor[i] = excl;
    g_dinv[i] = rsqrtf(g_deg[i]);
    if (i == NN - 1) g_rowptr[NN] = excl + c;
}

__global__ void k_fill(const float* __restrict__ ea, const int* __restrict__ ei) {
    int e = blockIdx.x * blockDim.x + threadIdx.x;
    if (e >= EE) return;
    int s = ei[e];
    int d = ei[EE + e];
    float nm = g_dinv[s] * ea[e] * g_dinv[d];
    int pos = atomicAdd(&g_cursor[d], 1);
    g_col[pos] = s;
    g_val[pos] = nm;
}

// ---------------- sparse aggregate: ax = (P + D^-1) x ----------------
__global__ void k_agg(const float* __restrict__ x) {
    int gw = (blockIdx.x * blockDim.x + threadIdx.x) >> 5;
    if (gw >= NN) return;
    int lane = threadIdx.x & 31;

    float di = g_dinv[gw];
    float self = di * di;
    float4 xv = __ldg(reinterpret_cast<const float4*>(x + (size_t)gw * FF) + lane);
    float4 a;
    a.x = self * xv.x; a.y = self * xv.y; a.z = self * xv.z; a.w = self * xv.w;

    int beg = g_rowptr[gw], end = g_rowptr[gw + 1];
    for (int j = beg; j < end; j++) {
        int s = g_col[j];
        float v = g_val[j];
        float4 xs = __ldg(reinterpret_cast<const float4*>(x + (size_t)s * FF) + lane);
        a.x += v * xs.x; a.y += v * xs.y; a.z += v * xs.z; a.w += v * xs.w;
    }
    reinterpret_cast<float4*>(g_ax + (size_t)gw * FF)[lane] = a;
}

// ================= Fused GRU: GEMM1 (z,r) + GEMM2 (cand) in one CTA =================
// BM=64 rows per CTA, 256 threads = 8 warps as 2x4 (wm in {0,1}, wn in {0..3}).
// GEMM1: [ax|h](64x256) @ Wzr(256x256) -> z (smem), hr (smem)
// GEMM2: [ax|hr](64x256) @ Whc(256x128) -> cand; epilogue updates g_h, g_out.
__global__ void __launch_bounds__(256, 2) k_gru() {
    extern __shared__ unsigned sm[];
    unsigned* As = sm;                               // [64][AS_STR]
    unsigned* Bs = sm + 64 * AS_STR;                 // [32][BSZ_STR] (reused stride 132 in GEMM2)
    float* hr_s = reinterpret_cast<float*>(sm + 64 * AS_STR + KC * BSZ_STR); // [64][HR_STR]
    float* z_s  = hr_s + 64 * HR_STR;                                        // [64][HR_STR]

    const int tid = threadIdx.x;
    const int w = tid >> 5, lane = tid & 31;
    const int wm = w & 1, wn = w >> 1;
    const int gid = lane >> 2, tig = lane & 3;
    const int row0 = blockIdx.x * 64;

    // ---------------- GEMM1: N=256 ----------------
    {
        float acc[2][8][4];
#pragma unroll
        for (int mt = 0; mt < 2; mt++)
#pragma unroll
            for (int nt = 0; nt < 8; nt++)
#pragma unroll
                for (int q = 0; q < 4; q++) acc[mt][nt][q] = 0.f;

#pragma unroll
        for (int chunk = 0; chunk < 8; chunk++) {
            const float* Ap = ((chunk < 4) ? g_ax : g_h)
                            + (size_t)row0 * FF + (chunk & 3) * KC;
#pragma unroll
            for (int t = 0; t < 2; t++) {
                int i = tid + t * 256;
                int r = i >> 3, j = i & 7;
                float4 v = __ldg(reinterpret_cast<const float4*>(Ap + (size_t)r * FF) + j);
                unsigned* dst = As + r * AS_STR + j * 4;
                dst[0] = f2tf(v.x); dst[1] = f2tf(v.y); dst[2] = f2tf(v.z); dst[3] = f2tf(v.w);
            }
            const uint4* Bp = reinterpret_cast<const uint4*>(g_Wzr + (size_t)chunk * KC * 256);
#pragma unroll
            for (int t = 0; t < 8; t++) {
                int i = tid + t * 256;
                int r = i >> 6, j = i & 63;
                uint4 v = Bp[r * 64 + j];
                *reinterpret_cast<uint4*>(Bs + r * BSZ_STR + j * 4) = v;
            }
            __syncthreads();

#pragma unroll
            for (int k8 = 0; k8 < 4; k8++) {
                int kk = k8 * 8;
                unsigned a[2][4];
#pragma unroll
                for (int mt = 0; mt < 2; mt++) {
                    int rb = wm * 32 + mt * 16 + gid;
                    a[mt][0] = As[rb * AS_STR + kk + tig];
                    a[mt][1] = As[(rb + 8) * AS_STR + kk + tig];
                    a[mt][2] = As[rb * AS_STR + kk + tig + 4];
                    a[mt][3] = As[(rb + 8) * AS_STR + kk + tig + 4];
                }
#pragma unroll
                for (int nt = 0; nt < 8; nt++) {
                    unsigned b[2];
                    int cb = wn * 64 + nt * 8 + gid;
                    b[0] = Bs[(kk + tig) * BSZ_STR + cb];
                    b[1] = Bs[(kk + tig + 4) * BSZ_STR + cb];
                    mma_tf32(acc[0][nt], a[0], b);
                    mma_tf32(acc[1][nt], a[1], b);
                }
            }
            __syncthreads();
        }

        // epilogue1: wn 0,1 -> z cols [0,128) to z_s; wn 2,3 -> hr cols to hr_s
#pragma unroll
        for (int mt = 0; mt < 2; mt++) {
#pragma unroll
            for (int nt = 0; nt < 8; nt++) {
                int col = wn * 64 + nt * 8 + 2 * tig;
                int lr1 = wm * 32 + mt * 16 + gid;
                int lr2 = lr1 + 8;
                float b0 = g_bias_zr[col], b1 = g_bias_zr[col + 1];
                if (wn < 2) {
                    int n = col;
                    z_s[lr1 * HR_STR + n]     = sigmoid_fast(acc[mt][nt][0] + b0);
                    z_s[lr1 * HR_STR + n + 1] = sigmoid_fast(acc[mt][nt][1] + b1);
                    z_s[lr2 * HR_STR + n]     = sigmoid_fast(acc[mt][nt][2] + b0);
                    z_s[lr2 * HR_STR + n + 1] = sigmoid_fast(acc[mt][nt][3] + b1);
                } else {
                    int n = col - 128;
                    float2 h1 = *reinterpret_cast<const float2*>(g_h + (size_t)(row0 + lr1) * FF + n);
                    float2 h2 = *reinterpret_cast<const float2*>(g_h + (size_t)(row0 + lr2) * FF + n);
                    hr_s[lr1 * HR_STR + n]     = sigmoid_fast(acc[mt][nt][0] + b0) * h1.x;
                    hr_s[lr1 * HR_STR + n + 1] = sigmoid_fast(acc[mt][nt][1] + b1) * h1.y;
                    hr_s[lr2 * HR_STR + n]     = sigmoid_fast(acc[mt][nt][2] + b0) * h2.x;
                    hr_s[lr2 * HR_STR + n + 1] = sigmoid_fast(acc[mt][nt][3] + b1) * h2.y;
                }
            }
        }
    }
    __syncthreads();   // z_s / hr_s visible to all warps

    // ---------------- GEMM2: N=128, A = [ax | hr_s] ----------------
    float acc[2][4][4];
#pragma unroll
    for (int mt = 0; mt < 2; mt++)
#pragma unroll
        for (int nt = 0; nt < 4; nt++)
#pragma unroll
            for (int q = 0; q < 4; q++) acc[mt][nt][q] = 0.f;

#pragma unroll
    for (int chunk = 0; chunk < 8; chunk++) {
        // stage B (32x128) always; stage A from g_ax only for chunks 0-3
        const uint4* Bp = reinterpret_cast<const uint4*>(g_Whc + (size_t)chunk * KC * 128);
#pragma unroll
        for (int t = 0; t < 4; t++) {
            int i = tid + t * 256;
            int r = i >> 5, j = i & 31;
            uint4 v = Bp[r * 32 + j];
            *reinterpret_cast<uint4*>(Bs + r * BSC_STR + j * 4) = v;
        }
        if (chunk < 4) {
            const float* Ap = g_ax + (size_t)row0 * FF + chunk * KC;
#pragma unroll
            for (int t = 0; t < 2; t++) {
                int i = tid + t * 256;
                int r = i >> 3, j = i & 7;
                float4 v = __ldg(reinterpret_cast<const float4*>(Ap + (size_t)r * FF) + j);
                unsigned* dst = As + r * AS_STR + j * 4;
                dst[0] = f2tf(v.x); dst[1] = f2tf(v.y); dst[2] = f2tf(v.z); dst[3] = f2tf(v.w);
            }
        }
        __syncthreads();

#pragma unroll
        for (int k8 = 0; k8 < 4; k8++) {
            int kk = k8 * 8;
            unsigned a[2][4];
#pragma unroll
            for (int mt = 0; mt < 2; mt++) {
                int rb = wm * 32 + mt * 16 + gid;
                if (chunk < 4) {
                    a[mt][0] = As[rb * AS_STR + kk + tig];
                    a[mt][1] = As[(rb + 8) * AS_STR + kk + tig];
                    a[mt][2] = As[rb * AS_STR + kk + tig + 4];
                    a[mt][3] = As[(rb + 8) * AS_STR + kk + tig + 4];
                } else {
                    int kcol = (chunk - 4) * KC + kk + tig;
                    a[mt][0] = f2tf(hr_s[rb * HR_STR + kcol]);
                    a[mt][1] = f2tf(hr_s[(rb + 8) * HR_STR + kcol]);
                    a[mt][2] = f2tf(hr_s[rb * HR_STR + kcol + 4]);
                    a[mt][3] = f2tf(hr_s[(rb + 8) * HR_STR + kcol + 4]);
                }
            }
#pragma unroll
            for (int nt = 0; nt < 4; nt++) {
                unsigned b[2];
                int cb = wn * 32 + nt * 8 + gid;
                b[0] = Bs[(kk + tig) * BSC_STR + cb];
                b[1] = Bs[(kk + tig + 4) * BSC_STR + cb];
                mma_tf32(acc[0][nt], a[0], b);
                mma_tf32(acc[1][nt], a[1], b);
            }
        }
        __syncthreads();
    }

    // epilogue2: cand = tanh(acc + bias); hn = (1-z)*hr; h = hn; out += hn + z*cand
#pragma unroll
    for (int mt = 0; mt < 2; mt++) {
#pragma unroll
        for (int nt = 0; nt < 4; nt++) {
            int n = wn * 32 + nt * 8 + 2 * tig;
            float b0 = g_bias_c[n], b1 = g_bias_c[n + 1];
#pragma unroll
            for (int half = 0; half < 2; half++) {
                int lr = wm * 32 + mt * 16 + gid + half * 8;
                int row = row0 + lr;
                float c0 = tanh_fast(acc[mt][nt][half * 2]     + b0);
                float c1 = tanh_fast(acc[mt][nt][half * 2 + 1] + b1);
                float z0 = z_s[lr * HR_STR + n];
                float z1 = z_s[lr * HR_STR + n + 1];
                float hr0 = hr_s[lr * HR_STR + n];
                float hr1 = hr_s[lr * HR_STR + n + 1];
                float2 hn = make_float2((1.f - z0) * hr0, (1.f - z1) * hr1);
                size_t idx = (size_t)row * FF + n;
                *reinterpret_cast<float2*>(g_h + idx) = hn;
                float2 ov = *reinterpret_cast<float2*>(g_out + idx);
                ov.x += hn.x + z0 * c0;
                ov.y += hn.y + z1 * c1;
                *reinterpret_cast<float2*>(g_out + idx) = ov;
            }
        }
    }
}

// ---------------- pooling + classifier ----------------
__global__ void k_pool(const float* __restrict__ Wlin, const float* __restrict__ blin,
                       float* __restrict__ y) {
    int g = blockIdx.x;
    int f = threadIdx.x;
    const float* base = g_out + (size_t)g * NPG * FF + f;
    float s = 0.f;
#pragma unroll 4
    for (int n = 0; n < NPG; n++) s += base[(size_t)n * FF];
    s *= (1.0f / (float)NPG);
    float p0 = s * __ldg(Wlin + 2 * f);
    float p1 = s * __ldg(Wlin + 2 * f + 1);
#pragma unroll
    for (int off = 16; off > 0; off >>= 1) {
        p0 += __shfl_down_sync(0xffffffffu, p0, off);
        p1 += __shfl_down_sync(0xffffffffu, p1, off);
    }
    __shared__ float r0s[4], r1s[4];
    int w = f >> 5, lane = f & 31;
    if (lane == 0) { r0s[w] = p0; r1s[w] = p1; }
    __syncthreads();
    if (f == 0) {
        y[2 * g]     = r0s[0] + r0s[1] + r0s[2] + r0s[3] + __ldg(blin);
        y[2 * g + 1] = r1s[0] + r1s[1] + r1s[2] + r1s[3] + __ldg(blin + 1);
    }
}

// ---------------- launch ----------------
extern "C" void kernel_launch(void* const* d_in, const int* in_sizes, int n_in,
                              void* d_out, int out_size) {
    const float* xs = nullptr;
    const float* eas = nullptr;
    const int*   eis = nullptr;
    const float* Wg[6] = {nullptr, nullptr, nullptr, nullptr, nullptr, nullptr};
    const float* bg[6] = {nullptr, nullptr, nullptr, nullptr, nullptr, nullptr};
    const float* Wlin = nullptr;
    const float* blin = nullptr;
    int wi = 0, bi = 0;
    for (int i = 0; i < n_in; i++) {
        long sz = in_sizes[i];
        void* p = d_in[i];
        if (sz == (long)TT * NN * FF)      xs  = (const float*)p;
        else if (sz == (long)TT * EE)      eas = (const float*)p;
        else if (sz == (long)2 * TT * EE)  eis = (const int*)p;
        else if (sz == (long)NN)           { /* batch: contiguous by construction */ }
        else if (sz == (long)FF * FF && wi < 6) Wg[wi++] = (const float*)p;
        else if (sz == (long)FF && bi < 6)      bg[bi++] = (const float*)p;
        else if (sz == (long)FF * CC)      Wlin = (const float*)p;
        else if (sz == (long)CC)           blin = (const float*)p;
    }
    float* y = (float*)d_out;

    const int SMEM_GRU = (64 * AS_STR + KC * BSZ_STR + 2 * 64 * HR_STR) * 4;  // 110080 B
    cudaFuncSetAttribute(k_gru, cudaFuncAttributeMaxDynamicSharedMemorySize, SMEM_GRU);

    k_init_hout<<<(NN * FF / 4 + 255) / 256, 256>>>();
    k_pack<<<(65536 + 32768 + 256 + 128 + 255) / 256, 256>>>(
        Wg[0], bg[0], Wg[1], bg[1], Wg[2], bg[2],
        Wg[3], bg[3], Wg[4], bg[4], Wg[5], bg[5]);

    for (int t = 0; t < TT; t++) {
        const float* x  = xs  + (size_t)t * NN * FF;
        const float* ea = eas + (size_t)t * EE;
        const int*   ei = eis + (size_t)t * 2 * EE;

        k_prep<<<(NN + 255) / 256, 256>>>();
        k_count<<<(EE + 255) / 256, 256>>>(ea, ei);
        k_scan1<<<NBLK, 256>>>();
        k_scan2<<<1, 512>>>();
        k_scan3<<<NBLK, 256>>>();
        k_fill<<<(EE + 255) / 256, 256>>>(ea, ei);
        k_agg<<<(NN * 32 + 255) / 256, 256>>>(x);
        k_gru<<<NN / 64, 256, SMEM_GRU>>>();
    }
    k_pool<<<BB, 128>>>(Wlin, blin, y);
}

// round 5
// speedup vs baseline: 4.0182x; 1.1483x over previous
#include <cuda_runtime.h>
#include <cstdint>

#define NN 113664
#define FF 128
#define EE 909312
#define TT 4
#define BB 1024
#define CC 2
#define NPG 111        // nodes per graph = NN/BB
#define NBLK 444       // NN / 256

// GEMM tiling
#define BM 128         // rows per CTA
#define KC 32          // K chunk
#define AS_STR 36      // As row stride (uints) -> conflict-free frags
#define BSZ_STR 264    // Bs stride GEMM1 (conflict-free: 264%32==8)
#define BSC_STR 136    // Bs stride GEMM2 (conflict-free: 136%32==8)
#define HR_STR 132     // z/hr smem stride (conflict-free frag reads)

// ---------------- device scratch (static: no runtime allocation) ----------------
__device__ float g_deg [TT * NN];
__device__ float g_dinv[TT * NN];
__device__ int   g_cnt [TT * NN];
__device__ int   g_rowptr[TT * (NN + 1)];
__device__ int   g_cursor[TT * NN];
__device__ int   g_bsum[TT * NBLK];
__device__ int   g_boff[TT * (NBLK + 1)];
__device__ int   g_col[TT * EE];
__device__ float g_val[TT * EE];
__device__ float g_ax [TT * NN * FF];
__device__ float g_h  [NN * FF];
__device__ float g_out[NN * FF];
__device__ unsigned g_Wzr[256 * 256];   // packed tf32 bits: [k][n]  n<128:z  n>=128:r
__device__ unsigned g_Whc[256 * 128];   // packed tf32 bits: [k][n]
__device__ float g_bias_zr[256];
__device__ float g_bias_c[128];

// ---------------- math helpers ----------------
__device__ __forceinline__ float tanh_fast(float x) {
    float y;
    asm("tanh.approx.f32 %0, %1;" : "=f"(y) : "f"(x));
    return y;
}
__device__ __forceinline__ float sigmoid_fast(float x) {
    return 0.5f * tanh_fast(0.5f * x) + 0.5f;
}
__device__ __forceinline__ unsigned f2tf(float x) {
    unsigned r;
    asm("cvt.rna.tf32.f32 %0, %1;" : "=r"(r) : "f"(x));
    return r;
}
__device__ __forceinline__ void mma_tf32(float d[4], const unsigned a[4], const unsigned b[2]) {
    asm volatile(
        "mma.sync.aligned.m16n8k8.row.col.f32.tf32.tf32.f32 "
        "{%0,%1,%2,%3}, {%4,%5,%6,%7}, {%8,%9}, {%0,%1,%2,%3};"
        : "+f"(d[0]), "+f"(d[1]), "+f"(d[2]), "+f"(d[3])
        : "r"(a[0]), "r"(a[1]), "r"(a[2]), "r"(a[3]), "r"(b[0]), "r"(b[1]));
}

// ---------------- init: h0 = eye(N,F), out = 0 ----------------
__global__ void k_init_hout() {
    int idx = blockIdx.x * blockDim.x + threadIdx.x;
    if (idx >= NN * FF / 4) return;
    float4 z4 = make_float4(0.f, 0.f, 0.f, 0.f);
    reinterpret_cast<float4*>(g_out)[idx] = z4;
    int base = idx * 4;
    int row = base >> 7;
    int col = base & 127;
    float4 h4 = z4;
    if (row < FF && row >= col && row <= col + 3) {
        (&h4.x)[row - col] = 1.0f;
    }
    reinterpret_cast<float4*>(g_h)[idx] = h4;
}

// ---------------- weight packing (once per launch) ----------------
__global__ void k_pack(const float* __restrict__ Wzi, const float* __restrict__ bzi,
                       const float* __restrict__ Wzh, const float* __restrict__ bzh,
                       const float* __restrict__ Wri, const float* __restrict__ bri,
                       const float* __restrict__ Wrh, const float* __restrict__ brh,
                       const float* __restrict__ Whi, const float* __restrict__ bhi,
                       const float* __restrict__ Whh, const float* __restrict__ bhh) {
    int i = blockIdx.x * blockDim.x + threadIdx.x;
    if (i < 65536) {
        int k = i >> 8, n = i & 255;
        float v;
        if (k < 128) v = (n < 128) ? Wzi[k * 128 + n] : Wri[k * 128 + (n - 128)];
        else         v = (n < 128) ? Wzh[(k - 128) * 128 + n] : Wrh[(k - 128) * 128 + (n - 128)];
        g_Wzr[i] = f2tf(v);
    } else if (i < 65536 + 32768) {
        int j = i - 65536;
        int k = j >> 7, n = j & 127;
        float v = (k < 128) ? Whi[k * 128 + n] : Whh[(k - 128) * 128 + n];
        g_Whc[j] = f2tf(v);
    } else if (i < 65536 + 32768 + 256) {
        int n = i - (65536 + 32768);
        g_bias_zr[n] = (n < 128) ? (bzi[n] + bzh[n]) : (bri[n - 128] + brh[n - 128]);
    } else if (i < 65536 + 32768 + 256 + 128) {
        int n = i - (65536 + 32768 + 256);
        g_bias_c[n] = bhi[n] + bhh[n];
    }
}

// ---------------- batched per-step CSR build (all TT steps at once) ----------------
__global__ void k_prep4() {
    int i = blockIdx.x * blockDim.x + threadIdx.x;
    if (i < TT * NN) { g_deg[i] = 1.0f; g_cnt[i] = 0; }
}

__global__ void k_count4(const float* __restrict__ eas, const int* __restrict__ eis) {
    int e = blockIdx.x * blockDim.x + threadIdx.x;
    int t = blockIdx.y;
    if (e >= EE) return;
    int d = eis[(size_t)t * 2 * EE + EE + e];
    atomicAdd(&g_deg[t * NN + d], eas[(size_t)t * EE + e]);
    atomicAdd(&g_cnt[t * NN + d], 1);
}

__global__ void k_scan1() {
    __shared__ int sh[256];
    int tid = threadIdx.x;
    int t = blockIdx.y;
    sh[tid] = g_cnt[t * NN + blockIdx.x * 256 + tid];
    __syncthreads();
#pragma unroll
    for (int off = 128; off > 0; off >>= 1) {
        if (tid < off) sh[tid] += sh[tid + off];
        __syncthreads();
    }
    if (tid == 0) g_bsum[t * NBLK + blockIdx.x] = sh[0];
}

__global__ void k_scan2() {
    __shared__ int sh[512];
    int tid = threadIdx.x;
    int t = blockIdx.x;
    int v = (tid < NBLK) ? g_bsum[t * NBLK + tid] : 0;
    sh[tid] = v;
    __syncthreads();
#pragma unroll
    for (int off = 1; off < 512; off <<= 1) {
        int u = (tid >= off) ? sh[tid - off] : 0;
        __syncthreads();
        sh[tid] += u;
        __syncthreads();
    }
    if (tid < NBLK) g_boff[t * (NBLK + 1) + tid] = sh[tid] - v;
    if (tid == NBLK - 1) g_boff[t * (NBLK + 1) + NBLK] = sh[tid];
}

__global__ void k_scan3() {
    __shared__ int sh[256];
    int tid = threadIdx.x;
    int t = blockIdx.y;
    int i = blockIdx.x * 256 + tid;
    int c = g_cnt[t * NN + i];
    sh[tid] = c;
    __syncthreads();
#pragma unroll
    for (int off = 1; off < 256; off <<= 1) {
        int u = (tid >= off) ? sh[tid - off] : 0;
        __syncthreads();
        sh[tid] += u;
        __syncthreads();
    }
    int excl = sh[tid] - c + g_boff[t * (NBLK + 1) + blockIdx.x];
    g_rowptr[t * (NN + 1) + i] = excl;
    g_cursor[t * NN + i] = excl;
    g_dinv[t * NN + i] = rsqrtf(g_deg[t * NN + i]);
    if (i == NN - 1) g_rowptr[t * (NN + 1) + NN] = excl + c;
}

__global__ void k_fill4(const float* __restrict__ eas, const int* __restrict__ eis) {
    int e = blockIdx.x * blockDim.x + threadIdx.x;
    int t = blockIdx.y;
    if (e >= EE) return;
    int s = eis[(size_t)t * 2 * EE + e];
    int d = eis[(size_t)t * 2 * EE + EE + e];
    float nm = g_dinv[t * NN + s] * eas[(size_t)t * EE + e] * g_dinv[t * NN + d];
    int pos = atomicAdd(&g_cursor[t * NN + d], 1);
    g_col[(size_t)t * EE + pos] = s;
    g_val[(size_t)t * EE + pos] = nm;
}

// ---------------- sparse aggregate for all steps: ax_t = (P_t + D_t^-1) x_t ----------------
__global__ void k_agg4(const float* __restrict__ xs) {
    int gw = (blockIdx.x * blockDim.x + threadIdx.x) >> 5;
    int t = blockIdx.y;
    if (gw >= NN) return;
    int lane = threadIdx.x & 31;

    const float* x = xs + (size_t)t * NN * FF;
    float di = g_dinv[t * NN + gw];
    float self = di * di;
    float4 xv = __ldg(reinterpret_cast<const float4*>(x + (size_t)gw * FF) + lane);
    float4 a;
    a.x = self * xv.x; a.y = self * xv.y; a.z = self * xv.z; a.w = self * xv.w;

    int beg = g_rowptr[t * (NN + 1) + gw], end = g_rowptr[t * (NN + 1) + gw + 1];
    const int* col = g_col + (size_t)t * EE;
    const float* val = g_val + (size_t)t * EE;
    for (int j = beg; j < end; j++) {
        int s = col[j];
        float v = val[j];
        float4 xsv = __ldg(reinterpret_cast<const float4*>(x + (size_t)s * FF) + lane);
        a.x += v * xsv.x; a.y += v * xsv.y; a.z += v * xsv.z; a.w += v * xsv.w;
    }
    reinterpret_cast<float4*>(g_ax + (size_t)t * NN * FF + (size_t)gw * FF)[lane] = a;
}

// ================= Fused GRU step: GEMM1 (z,r) + GEMM2 (cand), BM=128, 512 thr =================
// 16 warps as 4x4: wm in {0..3} (32-row groups), wn in {0..3}.
// GEMM1: [ax|h](128x256) @ Wzr(256x256) -> z (smem), hr (smem; h cached in smem during staging)
// GEMM2: [ax|hr](128x256) @ Whc(256x128) -> cand; epilogue updates g_h, g_out.
__global__ void __launch_bounds__(512, 1) k_gru(int step) {
    extern __shared__ unsigned sm[];
    unsigned* As = sm;                                   // [128][AS_STR]
    unsigned* Bs = sm + BM * AS_STR;                     // [32][BSZ_STR]
    float* hr_s = reinterpret_cast<float*>(sm + BM * AS_STR + KC * BSZ_STR); // [128][HR_STR]
    float* z_s  = hr_s + BM * HR_STR;                    // [128][HR_STR]

    const float* ax = g_ax + (size_t)step * NN * FF;
    const int tid = threadIdx.x;
    const int w = tid >> 5, lane = tid & 31;
    const int wm = w & 3, wn = w >> 2;
    const int gid = lane >> 2, tig = lane & 3;
    const int row0 = blockIdx.x * BM;

    // ---------------- GEMM1: N=256 ----------------
    {
        float acc[2][8][4];
#pragma unroll
        for (int mt = 0; mt < 2; mt++)
#pragma unroll
            for (int nt = 0; nt < 8; nt++)
#pragma unroll
                for (int q = 0; q < 4; q++) acc[mt][nt][q] = 0.f;

#pragma unroll
        for (int chunk = 0; chunk < 8; chunk++) {
            const float* Ap = ((chunk < 4) ? ax : g_h)
                            + (size_t)row0 * FF + (chunk & 3) * KC;
            // stage A: 128 rows x 8 float4 = 1024, 512 thr -> 2 iters
#pragma unroll
            for (int t = 0; t < 2; t++) {
                int i = tid + t * 512;
                int r = i >> 3, j = i & 7;
                float4 v = __ldg(reinterpret_cast<const float4*>(Ap + (size_t)r * FF) + j);
                unsigned* dst = As + r * AS_STR + j * 4;
                dst[0] = f2tf(v.x); dst[1] = f2tf(v.y); dst[2] = f2tf(v.z); dst[3] = f2tf(v.w);
                if (chunk >= 4) {      // cache raw h in hr_s for epilogue (saves global reread)
                    float* hd = hr_s + r * HR_STR + (chunk & 3) * KC + j * 4;
                    hd[0] = v.x; hd[1] = v.y; hd[2] = v.z; hd[3] = v.w;
                }
            }
            // stage B: 32x256 = 2048 uint4, 512 thr -> 4 iters
            const uint4* Bp = reinterpret_cast<const uint4*>(g_Wzr + (size_t)chunk * KC * 256);
#pragma unroll
            for (int t = 0; t < 4; t++) {
                int i = tid + t * 512;
                int r = i >> 6, j = i & 63;
                *reinterpret_cast<uint4*>(Bs + r * BSZ_STR + j * 4) = Bp[r * 64 + j];
            }
            __syncthreads();

#pragma unroll
            for (int k8 = 0; k8 < 4; k8++) {
                int kk = k8 * 8;
                unsigned a[2][4];
#pragma unroll
                for (int mt = 0; mt < 2; mt++) {
                    int rb = wm * 32 + mt * 16 + gid;
                    a[mt][0] = As[rb * AS_STR + kk + tig];
                    a[mt][1] = As[(rb + 8) * AS_STR + kk + tig];
                    a[mt][2] = As[rb * AS_STR + kk + tig + 4];
                    a[mt][3] = As[(rb + 8) * AS_STR + kk + tig + 4];
                }
#pragma unroll
                for (int nt = 0; nt < 8; nt++) {
                    unsigned b[2];
                    int cb = wn * 64 + nt * 8 + gid;
                    b[0] = Bs[(kk + tig) * BSZ_STR + cb];
                    b[1] = Bs[(kk + tig + 4) * BSZ_STR + cb];
                    mma_tf32(acc[0][nt], a[0], b);
                    mma_tf32(acc[1][nt], a[1], b);
                }
            }
            __syncthreads();
        }

        // epilogue1: wn 0,1 -> z cols [0,128) to z_s; wn 2,3 -> hr = sig(.)*h (h cached in hr_s)
#pragma unroll
        for (int mt = 0; mt < 2; mt++) {
#pragma unroll
            for (int nt = 0; nt < 8; nt++) {
                int col = wn * 64 + nt * 8 + 2 * tig;
                int lr1 = wm * 32 + mt * 16 + gid;
                int lr2 = lr1 + 8;
                float b0 = g_bias_zr[col], b1 = g_bias_zr[col + 1];
                if (wn < 2) {
                    int n = col;
                    z_s[lr1 * HR_STR + n]     = sigmoid_fast(acc[mt][nt][0] + b0);
                    z_s[lr1 * HR_STR + n + 1] = sigmoid_fast(acc[mt][nt][1] + b1);
                    z_s[lr2 * HR_STR + n]     = sigmoid_fast(acc[mt][nt][2] + b0);
                    z_s[lr2 * HR_STR + n + 1] = sigmoid_fast(acc[mt][nt][3] + b1);
                } else {
                    int n = col - 128;
                    float h10 = hr_s[lr1 * HR_STR + n],  h11 = hr_s[lr1 * HR_STR + n + 1];
                    float h20 = hr_s[lr2 * HR_STR + n],  h21 = hr_s[lr2 * HR_STR + n + 1];
                    hr_s[lr1 * HR_STR + n]     = sigmoid_fast(acc[mt][nt][0] + b0) * h10;
                    hr_s[lr1 * HR_STR + n + 1] = sigmoid_fast(acc[mt][nt][1] + b1) * h11;
                    hr_s[lr2 * HR_STR + n]     = sigmoid_fast(acc[mt][nt][2] + b0) * h20;
                    hr_s[lr2 * HR_STR + n + 1] = sigmoid_fast(acc[mt][nt][3] + b1) * h21;
                }
            }
        }
    }
    __syncthreads();   // z_s / hr_s visible to all warps

    // ---------------- GEMM2: N=128, A = [ax | hr_s] ----------------
    float acc[2][4][4];
#pragma unroll
    for (int mt = 0; mt < 2; mt++)
#pragma unroll
        for (int nt = 0; nt < 4; nt++)
#pragma unroll
            for (int q = 0; q < 4; q++) acc[mt][nt][q] = 0.f;

#pragma unroll
    for (int chunk = 0; chunk < 8; chunk++) {
        const uint4* Bp = reinterpret_cast<const uint4*>(g_Whc + (size_t)chunk * KC * 128);
#pragma unroll
        for (int t = 0; t < 2; t++) {
            int i = tid + t * 512;
            int r = i >> 5, j = i & 31;
            *reinterpret_cast<uint4*>(Bs + r * BSC_STR + j * 4) = Bp[r * 32 + j];
        }
        if (chunk < 4) {
            const float* Ap = ax + (size_t)row0 * FF + chunk * KC;
#pragma unroll
            for (int t = 0; t < 2; t++) {
                int i = tid + t * 512;
                int r = i >> 3, j = i & 7;
                float4 v = __ldg(reinterpret_cast<const float4*>(Ap + (size_t)r * FF) + j);
                unsigned* dst = As + r * AS_STR + j * 4;
                dst[0] = f2tf(v.x); dst[1] = f2tf(v.y); dst[2] = f2tf(v.z); dst[3] = f2tf(v.w);
            }
        }
        __syncthreads();

#pragma unroll
        for (int k8 = 0; k8 < 4; k8++) {
            int kk = k8 * 8;
            unsigned a[2][4];
#pragma unroll
            for (int mt = 0; mt < 2; mt++) {
                int rb = wm * 32 + mt * 16 + gid;
                if (chunk < 4) {
                    a[mt][0] = As[rb * AS_STR + kk + tig];
                    a[mt][1] = As[(rb + 8) * AS_STR + kk + tig];
                    a[mt][2] = As[rb * AS_STR + kk + tig + 4];
                    a[mt][3] = As[(rb + 8) * AS_STR + kk + tig + 4];
                } else {
                    int kcol = (chunk - 4) * KC + kk + tig;
                    a[mt][0] = f2tf(hr_s[rb * HR_STR + kcol]);
                    a[mt][1] = f2tf(hr_s[(rb + 8) * HR_STR + kcol]);
                    a[mt][2] = f2tf(hr_s[rb * HR_STR + kcol + 4]);
                    a[mt][3] = f2tf(hr_s[(rb + 8) * HR_STR + kcol + 4]);
                }
            }
#pragma unroll
            for (int nt = 0; nt < 4; nt++) {
                unsigned b[2];
                int cb = wn * 32 + nt * 8 + gid;
                b[0] = Bs[(kk + tig) * BSC_STR + cb];
                b[1] = Bs[(kk + tig + 4) * BSC_STR + cb];
                mma_tf32(acc[0][nt], a[0], b);
                mma_tf32(acc[1][nt], a[1], b);
            }
        }
        __syncthreads();
    }

    // epilogue2: cand = tanh(acc + bias); hn = (1-z)*hr; h = hn; out += hn + z*cand
#pragma unroll
    for (int mt = 0; mt < 2; mt++) {
#pragma unroll
        for (int nt = 0; nt < 4; nt++) {
            int n = wn * 32 + nt * 8 + 2 * tig;
            float b0 = g_bias_c[n], b1 = g_bias_c[n + 1];
#pragma unroll
            for (int half = 0; half < 2; half++) {
                int lr = wm * 32 + mt * 16 + gid + half * 8;
                int row = row0 + lr;
                float c0 = tanh_fast(acc[mt][nt][half * 2]     + b0);
                float c1 = tanh_fast(acc[mt][nt][half * 2 + 1] + b1);
                float z0 = z_s[lr * HR_STR + n];
                float z1 = z_s[lr * HR_STR + n + 1];
                float hr0 = hr_s[lr * HR_STR + n];
                float hr1 = hr_s[lr * HR_STR + n + 1];
                float2 hn = make_float2((1.f - z0) * hr0, (1.f - z1) * hr1);
                size_t idx = (size_t)row * FF + n;
                *reinterpret_cast<float2*>(g_h + idx) = hn;
                float2 ov = *reinterpret_cast<float2*>(g_out + idx);
                ov.x += hn.x + z0 * c0;
                ov.y += hn.y + z1 * c1;
                *reinterpret_cast<float2*>(g_out + idx) = ov;
            }
        }
    }
}

// ---------------- pooling + classifier ----------------
__global__ void k_pool(const float* __restrict__ Wlin, const float* __restrict__ blin,
                       float* __restrict__ y) {
    int g = blockIdx.x;
    int f = threadIdx.x;
    const float* base = g_out + (size_t)g * NPG * FF + f;
    float s = 0.f;
#pragma unroll 4
    for (int n = 0; n < NPG; n++) s += base[(size_t)n * FF];
    s *= (1.0f / (float)NPG);
    float p0 = s * __ldg(Wlin + 2 * f);
    float p1 = s * __ldg(Wlin + 2 * f + 1);
#pragma unroll
    for (int off = 16; off > 0; off >>= 1) {
        p0 += __shfl_down_sync(0xffffffffu, p0, off);
        p1 += __shfl_down_sync(0xffffffffu, p1, off);
    }
    __shared__ float r0s[4], r1s[4];
    int w = f >> 5, lane = f & 31;
    if (lane == 0) { r0s[w] = p0; r1s[w] = p1; }
    __syncthreads();
    if (f == 0) {
        y[2 * g]     = r0s[0] + r0s[1] + r0s[2] + r0s[3] + __ldg(blin);
        y[2 * g + 1] = r1s[0] + r1s[1] + r1s[2] + r1s[3] + __ldg(blin + 1);
    }
}

// ---------------- launch ----------------
extern "C" void kernel_launch(void* const* d_in, const int* in_sizes, int n_in,
                              void* d_out, int out_size) {
    const float* xs = nullptr;
    const float* eas = nullptr;
    const int*   eis = nullptr;
    const float* Wg[6] = {nullptr, nullptr, nullptr, nullptr, nullptr, nullptr};
    const float* bg[6] = {nullptr, nullptr, nullptr, nullptr, nullptr, nullptr};
    const float* Wlin = nullptr;
    const float* blin = nullptr;
    int wi = 0, bi = 0;
    for (int i = 0; i < n_in; i++) {
        long sz = in_sizes[i];
        void* p = d_in[i];
        if (sz == (long)TT * NN * FF)      xs  = (const float*)p;
        else if (sz == (long)TT * EE)      eas = (const float*)p;
        else if (sz == (long)2 * TT * EE)  eis = (const int*)p;
        else if (sz == (long)NN)           { /* batch: contiguous by construction */ }
        else if (sz == (long)FF * FF && wi < 6) Wg[wi++] = (const float*)p;
        else if (sz == (long)FF && bi < 6)      bg[bi++] = (const float*)p;
        else if (sz == (long)FF * CC)      Wlin = (const float*)p;
        else if (sz == (long)CC)           blin = (const float*)p;
    }
    float* y = (float*)d_out;

    const int SMEM_GRU = (BM * AS_STR + KC * BSZ_STR + 2 * BM * HR_STR) * 4;  // 187392 B
    cudaFuncSetAttribute(k_gru, cudaFuncAttributeMaxDynamicSharedMemorySize, SMEM_GRU);

    k_init_hout<<<(NN * FF / 4 + 255) / 256, 256>>>();
    k_pack<<<(65536 + 32768 + 256 + 128 + 255) / 256, 256>>>(
        Wg[0], bg[0], Wg[1], bg[1], Wg[2], bg[2],
        Wg[3], bg[3], Wg[4], bg[4], Wg[5], bg[5]);

    // h-independent pipeline, batched over all 4 timesteps
    k_prep4<<<(TT * NN + 255) / 256, 256>>>();
    k_count4<<<dim3((EE + 255) / 256, TT), 256>>>(eas, eis);
    k_scan1<<<dim3(NBLK, TT), 256>>>();
    k_scan2<<<TT, 512>>>();
    k_scan3<<<dim3(NBLK, TT), 256>>>();
    k_fill4<<<dim3((EE + 255) / 256, TT), 256>>>(eas, eis);
    k_agg4<<<dim3((NN * 32 + 255) / 256, TT), 256>>>(xs);

    // sequential GRU steps (h dependency)
    for (int t = 0; t < TT; t++)
        k_gru<<<NN / BM, 512, SMEM_GRU>>>(t);

    k_pool<<<BB, 128>>>(Wlin, blin, y);
}

// round 6
// speedup vs baseline: 4.1878x; 1.0422x over previous
#include <cuda_runtime.h>
#include <cstdint>

#define NN 113664
#define FF 128
#define EE 909312
#define TT 4
#define BB 1024
#define CC 2
#define NPG 111        // nodes per graph = NN/BB
#define NBLK 444       // NN / 256

// GEMM tiling
#define BM 128         // rows per CTA
#define KC 32          // K chunk
#define AS_STR 36      // As row stride (uints) -> conflict-free frags
#define BSZ_STR 264    // Bs stride GEMM1
#define BSC_STR 136    // Bs stride GEMM2
#define HR_STR 132     // z/hr smem stride

// ---------------- device scratch (static: no runtime allocation) ----------------
__device__ float g_dinv[TT * NN];
__device__ int   g_cnt [TT * NN];
__device__ int   g_rowptr[TT * (NN + 1)];
__device__ int   g_cursor[TT * NN];
__device__ int   g_bsum[TT * NBLK];
__device__ int   g_boff[TT * (NBLK + 1)];
__device__ int   g_col[TT * EE];
__device__ float g_val[TT * EE];
__device__ float g_ax [TT * NN * FF];
__device__ float g_h  [NN * FF];
__device__ float g_out[NN * FF];
__device__ unsigned g_Wzr[256 * 256];   // packed tf32 bits: [k][n]  n<128:z  n>=128:r
__device__ unsigned g_Whc[256 * 128];   // packed tf32 bits: [k][n]
__device__ float g_bias_zr[256];
__device__ float g_bias_c[128];

// ---------------- math helpers ----------------
__device__ __forceinline__ float tanh_fast(float x) {
    float y;
    asm("tanh.approx.f32 %0, %1;" : "=f"(y) : "f"(x));
    return y;
}
__device__ __forceinline__ float sigmoid_fast(float x) {
    return 0.5f * tanh_fast(0.5f * x) + 0.5f;
}
__device__ __forceinline__ unsigned f2tf(float x) {
    unsigned r;
    asm("cvt.rna.tf32.f32 %0, %1;" : "=r"(r) : "f"(x));
    return r;
}
__device__ __forceinline__ void mma_tf32(float d[4], const unsigned a[4], const unsigned b[2]) {
    asm volatile(
        "mma.sync.aligned.m16n8k8.row.col.f32.tf32.tf32.f32 "
        "{%0,%1,%2,%3}, {%4,%5,%6,%7}, {%8,%9}, {%0,%1,%2,%3};"
        : "+f"(d[0]), "+f"(d[1]), "+f"(d[2]), "+f"(d[3])
        : "r"(a[0]), "r"(a[1]), "r"(a[2]), "r"(a[3]), "r"(b[0]), "r"(b[1]));
}

// ---------------- init: h0 = eye(N,F), out = 0 ----------------
__global__ void k_init_hout() {
    int idx = blockIdx.x * blockDim.x + threadIdx.x;
    if (idx >= NN * FF / 4) return;
    float4 z4 = make_float4(0.f, 0.f, 0.f, 0.f);
    reinterpret_cast<float4*>(g_out)[idx] = z4;
    int base = idx * 4;
    int row = base >> 7;
    int col = base & 127;
    float4 h4 = z4;
    if (row < FF && row >= col && row <= col + 3) {
        (&h4.x)[row - col] = 1.0f;
    }
    reinterpret_cast<float4*>(g_h)[idx] = h4;
}

// ---------------- weight packing (once per launch) ----------------
__global__ void k_pack(const float* __restrict__ Wzi, const float* __restrict__ bzi,
                       const float* __restrict__ Wzh, const float* __restrict__ bzh,
                       const float* __restrict__ Wri, const float* __restrict__ bri,
                       const float* __restrict__ Wrh, const float* __restrict__ brh,
                       const float* __restrict__ Whi, const float* __restrict__ bhi,
                       const float* __restrict__ Whh, const float* __restrict__ bhh) {
    int i = blockIdx.x * blockDim.x + threadIdx.x;
    if (i < 65536) {
        int k = i >> 8, n = i & 255;
        float v;
        if (k < 128) v = (n < 128) ? Wzi[k * 128 + n] : Wri[k * 128 + (n - 128)];
        else         v = (n < 128) ? Wzh[(k - 128) * 128 + n] : Wrh[(k - 128) * 128 + (n - 128)];
        g_Wzr[i] = f2tf(v);
    } else if (i < 65536 + 32768) {
        int j = i - 65536;
        int k = j >> 7, n = j & 127;
        float v = (k < 128) ? Whi[k * 128 + n] : Whh[(k - 128) * 128 + n];
        g_Whc[j] = f2tf(v);
    } else if (i < 65536 + 32768 + 256) {
        int n = i - (65536 + 32768);
        g_bias_zr[n] = (n < 128) ? (bzi[n] + bzh[n]) : (bri[n - 128] + brh[n - 128]);
    } else if (i < 65536 + 32768 + 256 + 128) {
        int n = i - (65536 + 32768 + 256);
        g_bias_c[n] = bhi[n] + bhh[n];
    }
}

// ---------------- batched per-step CSR build (all TT steps at once) ----------------
__global__ void k_prep4() {
    int i = blockIdx.x * blockDim.x + threadIdx.x;
    if (i < TT * NN) g_cnt[i] = 0;
}

__global__ void k_cnt4(const int* __restrict__ eis) {
    int e = blockIdx.x * blockDim.x + threadIdx.x;
    int t = blockIdx.y;
    if (e >= EE) return;
    int d = eis[(size_t)t * 2 * EE + EE + e];
    atomicAdd(&g_cnt[t * NN + d], 1);
}

__global__ void k_scan1() {
    __shared__ int sh[256];
    int tid = threadIdx.x;
    int t = blockIdx.y;
    sh[tid] = g_cnt[t * NN + blockIdx.x * 256 + tid];
    __syncthreads();
#pragma unroll
    for (int off = 128; off > 0; off >>= 1) {
        if (tid < off) sh[tid] += sh[tid + off];
        __syncthreads();
    }
    if (tid == 0) g_bsum[t * NBLK + blockIdx.x] = sh[0];
}

__global__ void k_scan2() {
    __shared__ int sh[512];
    int tid = threadIdx.x;
    int t = blockIdx.x;
    int v = (tid < NBLK) ? g_bsum[t * NBLK + tid] : 0;
    sh[tid] = v;
    __syncthreads();
#pragma unroll
    for (int off = 1; off < 512; off <<= 1) {
        int u = (tid >= off) ? sh[tid - off] : 0;
        __syncthreads();
        sh[tid] += u;
        __syncthreads();
    }
    if (tid < NBLK) g_boff[t * (NBLK + 1) + tid] = sh[tid] - v;
    if (tid == NBLK - 1) g_boff[t * (NBLK + 1) + NBLK] = sh[tid];
}

__global__ void k_scan3() {
    __shared__ int sh[256];
    int tid = threadIdx.x;
    int t = blockIdx.y;
    int i = blockIdx.x * 256 + tid;
    int c = g_cnt[t * NN + i];
    sh[tid] = c;
    __syncthreads();
#pragma unroll
    for (int off = 1; off < 256; off <<= 1) {
        int u = (tid >= off) ? sh[tid - off] : 0;
        __syncthreads();
        sh[tid] += u;
        __syncthreads();
    }
    int excl = sh[tid] - c + g_boff[t * (NBLK + 1) + blockIdx.x];
    g_rowptr[t * (NN + 1) + i] = excl;
    g_cursor[t * NN + i] = excl;
    if (i == NN - 1) g_rowptr[t * (NN + 1) + NN] = excl + c;
}

__global__ void k_fill4(const float* __restrict__ eas, const int* __restrict__ eis) {
    int e = blockIdx.x * blockDim.x + threadIdx.x;
    int t = blockIdx.y;
    if (e >= EE) return;
    int s = eis[(size_t)t * 2 * EE + e];
    int d = eis[(size_t)t * 2 * EE + EE + e];
    int pos = atomicAdd(&g_cursor[t * NN + d], 1);
    g_col[(size_t)t * EE + pos] = s;
    g_val[(size_t)t * EE + pos] = eas[(size_t)t * EE + e];   // raw edge weight
}

// deg_i = 1 + sum of incoming edge weights (contiguous CSR scan); dinv = rsqrt(deg)
__global__ void k_deg4() {
    int i = blockIdx.x * blockDim.x + threadIdx.x;
    if (i >= TT * NN) return;
    int t = i / NN;
    int nidx = i - t * NN;
    int beg = g_rowptr[t * (NN + 1) + nidx], end = g_rowptr[t * (NN + 1) + nidx + 1];
    const float* val = g_val + (size_t)t * EE;
    float s = 1.0f;
    for (int j = beg; j < end; j++) s += val[j];
    g_dinv[i] = rsqrtf(s);
}

// ---------------- sparse aggregate for all steps: ax_t = (P_t + D_t^-1) x_t ----------------
__global__ void k_agg4(const float* __restrict__ xs) {
    int gw = (blockIdx.x * blockDim.x + threadIdx.x) >> 5;
    int t = blockIdx.y;
    if (gw >= NN) return;
    int lane = threadIdx.x & 31;

    const float* x = xs + (size_t)t * NN * FF;
    float dinv_d = g_dinv[t * NN + gw];
    float self = dinv_d * dinv_d;
    float4 xv = __ldg(reinterpret_cast<const float4*>(x + (size_t)gw * FF) + lane);

    float4 a = make_float4(0.f, 0.f, 0.f, 0.f);
    int beg = g_rowptr[t * (NN + 1) + gw], end = g_rowptr[t * (NN + 1) + gw + 1];
    const int* col = g_col + (size_t)t * EE;
    const float* val = g_val + (size_t)t * EE;
    const float* dinv = g_dinv + t * NN;
    for (int j = beg; j < end; j++) {
        int s = col[j];
        float v = val[j] * dinv[s];
        float4 xsv = __ldg(reinterpret_cast<const float4*>(x + (size_t)s * FF) + lane);
        a.x += v * xsv.x; a.y += v * xsv.y; a.z += v * xsv.z; a.w += v * xsv.w;
    }
    a.x = dinv_d * a.x + self * xv.x;
    a.y = dinv_d * a.y + self * xv.y;
    a.z = dinv_d * a.z + self * xv.z;
    a.w = dinv_d * a.w + self * xv.w;
    reinterpret_cast<float4*>(g_ax + (size_t)t * NN * FF + (size_t)gw * FF)[lane] = a;
}

// ================= Fused GRU step (register-prefetch pipelined), BM=128, 512 thr =================
// 16 warps as 4x4: wm in {0..3} (32-row groups), wn in {0..3}.
// GEMM1: [ax|h](128x256) @ Wzr(256x256) -> z (smem), hr (smem; raw h cached during staging)
// GEMM2: [ax|hr](128x256) @ Whc(256x128) -> cand; epilogue updates g_h, g_out.
__global__ void __launch_bounds__(512, 1) k_gru(int step) {
    extern __shared__ unsigned sm[];
    unsigned* As = sm;                                   // [128][AS_STR]
    unsigned* Bs = sm + BM * AS_STR;                     // [32][BSZ_STR]
    float* hr_s = reinterpret_cast<float*>(sm + BM * AS_STR + KC * BSZ_STR); // [128][HR_STR]
    float* z_s  = hr_s + BM * HR_STR;                    // [128][HR_STR]

    const float* ax = g_ax + (size_t)step * NN * FF;
    const int tid = threadIdx.x;
    const int w = tid >> 5, lane = tid & 31;
    const int wm = w & 3, wn = w >> 2;
    const int gid = lane >> 2, tig = lane & 3;
    const int row0 = blockIdx.x * BM;
    const int ar = tid >> 3, aj = tid & 7;   // A staging: rows ar, ar+64; float4 col aj

    // ---------------- GEMM1: N=256 ----------------
    {
        float acc[2][8][4];
#pragma unroll
        for (int mt = 0; mt < 2; mt++)
#pragma unroll
            for (int nt = 0; nt < 8; nt++)
#pragma unroll
                for (int q = 0; q < 4; q++) acc[mt][nt][q] = 0.f;

        // prologue: load chunk 0 into regs
        float4 av0, av1;
        uint4 bv0, bv1, bv2, bv3;
        {
            const float* Ap = ax + (size_t)row0 * FF;
            av0 = __ldg(reinterpret_cast<const float4*>(Ap + (size_t)ar * FF) + aj);
            av1 = __ldg(reinterpret_cast<const float4*>(Ap + (size_t)(ar + 64) * FF) + aj);
            const uint4* Bp = reinterpret_cast<const uint4*>(g_Wzr);
            bv0 = Bp[tid]; bv1 = Bp[tid + 512]; bv2 = Bp[tid + 1024]; bv3 = Bp[tid + 1536];
        }

#pragma unroll
        for (int chunk = 0; chunk < 8; chunk++) {
            // store staged regs -> smem
            {
                unsigned* d0 = As + ar * AS_STR + aj * 4;
                d0[0] = f2tf(av0.x); d0[1] = f2tf(av0.y); d0[2] = f2tf(av0.z); d0[3] = f2tf(av0.w);
                unsigned* d1 = As + (ar + 64) * AS_STR + aj * 4;
                d1[0] = f2tf(av1.x); d1[1] = f2tf(av1.y); d1[2] = f2tf(av1.z); d1[3] = f2tf(av1.w);
                if (chunk >= 4) {     // cache raw h for epilogue1
                    float* h0 = hr_s + ar * HR_STR + (chunk & 3) * KC + aj * 4;
                    h0[0] = av0.x; h0[1] = av0.y; h0[2] = av0.z; h0[3] = av0.w;
                    float* h1 = hr_s + (ar + 64) * HR_STR + (chunk & 3) * KC + aj * 4;
                    h1[0] = av1.x; h1[1] = av1.y; h1[2] = av1.z; h1[3] = av1.w;
                }
                int i0 = tid;
                *reinterpret_cast<uint4*>(Bs + (i0 >> 6) * BSZ_STR + (i0 & 63) * 4) = bv0;
                int i1 = tid + 512;
                *reinterpret_cast<uint4*>(Bs + (i1 >> 6) * BSZ_STR + (i1 & 63) * 4) = bv1;
                int i2 = tid + 1024;
                *reinterpret_cast<uint4*>(Bs + (i2 >> 6) * BSZ_STR + (i2 & 63) * 4) = bv2;
                int i3 = tid + 1536;
                *reinterpret_cast<uint4*>(Bs + (i3 >> 6) * BSZ_STR + (i3 & 63) * 4) = bv3;
            }
            __syncthreads();

            // prefetch next chunk (LDGs overlap the MMA loop below)
            if (chunk < 7) {
                int nc = chunk + 1;
                const float* Ap = ((nc < 4) ? ax : g_h) + (size_t)row0 * FF + (nc & 3) * KC;
                av0 = __ldg(reinterpret_cast<const float4*>(Ap + (size_t)ar * FF) + aj);
                av1 = __ldg(reinterpret_cast<const float4*>(Ap + (size_t)(ar + 64) * FF) + aj);
                const uint4* Bp = reinterpret_cast<const uint4*>(g_Wzr + (size_t)nc * KC * 256);
                bv0 = Bp[tid]; bv1 = Bp[tid + 512]; bv2 = Bp[tid + 1024]; bv3 = Bp[tid + 1536];
            }

#pragma unroll
            for (int k8 = 0; k8 < 4; k8++) {
                int kk = k8 * 8;
                unsigned a[2][4];
#pragma unroll
                for (int mt = 0; mt < 2; mt++) {
                    int rb = wm * 32 + mt * 16 + gid;
                    a[mt][0] = As[rb * AS_STR + kk + tig];
                    a[mt][1] = As[(rb + 8) * AS_STR + kk + tig];
                    a[mt][2] = As[rb * AS_STR + kk + tig + 4];
                    a[mt][3] = As[(rb + 8) * AS_STR + kk + tig + 4];
                }
#pragma unroll
                for (int nt = 0; nt < 8; nt++) {
                    unsigned b[2];
                    int cb = wn * 64 + nt * 8 + gid;
                    b[0] = Bs[(kk + tig) * BSZ_STR + cb];
                    b[1] = Bs[(kk + tig + 4) * BSZ_STR + cb];
                    mma_tf32(acc[0][nt], a[0], b);
                    mma_tf32(acc[1][nt], a[1], b);
                }
            }
            __syncthreads();
        }

        // epilogue1: wn 0,1 -> z cols [0,128) to z_s; wn 2,3 -> hr = sig(.)*h (h cached in hr_s)
#pragma unroll
        for (int mt = 0; mt < 2; mt++) {
#pragma unroll
            for (int nt = 0; nt < 8; nt++) {
                int col = wn * 64 + nt * 8 + 2 * tig;
                int lr1 = wm * 32 + mt * 16 + gid;
                int lr2 = lr1 + 8;
                float b0 = g_bias_zr[col], b1 = g_bias_zr[col + 1];
                if (wn < 2) {
                    int n = col;
                    z_s[lr1 * HR_STR + n]     = sigmoid_fast(acc[mt][nt][0] + b0);
                    z_s[lr1 * HR_STR + n + 1] = sigmoid_fast(acc[mt][nt][1] + b1);
                    z_s[lr2 * HR_STR + n]     = sigmoid_fast(acc[mt][nt][2] + b0);
                    z_s[lr2 * HR_STR + n + 1] = sigmoid_fast(acc[mt][nt][3] + b1);
                } else {
                    int n = col - 128;
                    float h10 = hr_s[lr1 * HR_STR + n],  h11 = hr_s[lr1 * HR_STR + n + 1];
                    float h20 = hr_s[lr2 * HR_STR + n],  h21 = hr_s[lr2 * HR_STR + n + 1];
                    hr_s[lr1 * HR_STR + n]     = sigmoid_fast(acc[mt][nt][0] + b0) * h10;
                    hr_s[lr1 * HR_STR + n + 1] = sigmoid_fast(acc[mt][nt][1] + b1) * h11;
                    hr_s[lr2 * HR_STR + n]     = sigmoid_fast(acc[mt][nt][2] + b0) * h20;
                    hr_s[lr2 * HR_STR + n + 1] = sigmoid_fast(acc[mt][nt][3] + b1) * h21;
                }
            }
        }
    }
    __syncthreads();   // z_s / hr_s visible to all warps

    // ---------------- GEMM2: N=128, A = [ax | hr_s] ----------------
    float acc[2][4][4];
#pragma unroll
    for (int mt = 0; mt < 2; mt++)
#pragma unroll
        for (int nt = 0; nt < 4; nt++)
#pragma unroll
            for (int q = 0; q < 4; q++) acc[mt][nt][q] = 0.f;

    float4 av0, av1;
    uint4 bv0, bv1;
    {
        const float* Ap = ax + (size_t)row0 * FF;
        av0 = __ldg(reinterpret_cast<const float4*>(Ap + (size_t)ar * FF) + aj);
        av1 = __ldg(reinterpret_cast<const float4*>(Ap + (size_t)(ar + 64) * FF) + aj);
        const uint4* Bp = reinterpret_cast<const uint4*>(g_Whc);
        bv0 = Bp[tid]; bv1 = Bp[tid + 512];
    }

#pragma unroll
    for (int chunk = 0; chunk < 8; chunk++) {
        // store staged regs
        if (chunk < 4) {
            unsigned* d0 = As + ar * AS_STR + aj * 4;
            d0[0] = f2tf(av0.x); d0[1] = f2tf(av0.y); d0[2] = f2tf(av0.z); d0[3] = f2tf(av0.w);
            unsigned* d1 = As + (ar + 64) * AS_STR + aj * 4;
            d1[0] = f2tf(av1.x); d1[1] = f2tf(av1.y); d1[2] = f2tf(av1.z); d1[3] = f2tf(av1.w);
        }
        {
            int i0 = tid;
            *reinterpret_cast<uint4*>(Bs + (i0 >> 5) * BSC_STR + (i0 & 31) * 4) = bv0;
            int i1 = tid + 512;
            *reinterpret_cast<uint4*>(Bs + (i1 >> 5) * BSC_STR + (i1 & 31) * 4) = bv1;
        }
        __syncthreads();

        if (chunk < 7) {
            int nc = chunk + 1;
            const uint4* Bp = reinterpret_cast<const uint4*>(g_Whc + (size_t)nc * KC * 128);
            bv0 = Bp[tid]; bv1 = Bp[tid + 512];
            if (nc < 4) {
                const float* Ap = ax + (size_t)row0 * FF + nc * KC;
                av0 = __ldg(reinterpret_cast<const float4*>(Ap + (size_t)ar * FF) + aj);
                av1 = __ldg(reinterpret_cast<const float4*>(Ap + (size_t)(ar + 64) * FF) + aj);
            }
        }

#pragma unroll
        for (int k8 = 0; k8 < 4; k8++) {
            int kk = k8 * 8;
            unsigned a[2][4];
#pragma unroll
            for (int mt = 0; mt < 2; mt++) {
                int rb = wm * 32 + mt * 16 + gid;
                if (chunk < 4) {
                    a[mt][0] = As[rb * AS_STR + kk + tig];
                    a[mt][1] = As[(rb + 8) * AS_STR + kk + tig];
                    a[mt][2] = As[rb * AS_STR + kk + tig + 4];
                    a[mt][3] = As[(rb + 8) * AS_STR + kk + tig + 4];
                } else {
                    int kcol = (chunk - 4) * KC + kk + tig;
                    a[mt][0] = f2tf(hr_s[rb * HR_STR + kcol]);
                    a[mt][1] = f2tf(hr_s[(rb + 8) * HR_STR + kcol]);
                    a[mt][2] = f2tf(hr_s[rb * HR_STR + kcol + 4]);
                    a[mt][3] = f2tf(hr_s[(rb + 8) * HR_STR + kcol + 4]);
                }
            }
#pragma unroll
            for (int nt = 0; nt < 4; nt++) {
                unsigned b[2];
                int cb = wn * 32 + nt * 8 + gid;
                b[0] = Bs[(kk + tig) * BSC_STR + cb];
                b[1] = Bs[(kk + tig + 4) * BSC_STR + cb];
                mma_tf32(acc[0][nt], a[0], b);
                mma_tf32(acc[1][nt], a[1], b);
            }
        }
        __syncthreads();
    }

    // epilogue2: cand = tanh(acc + bias); hn = (1-z)*hr; h = hn; out += hn + z*cand
#pragma unroll
    for (int mt = 0; mt < 2; mt++) {
#pragma unroll
        for (int nt = 0; nt < 4; nt++) {
            int n = wn * 32 + nt * 8 + 2 * tig;
            float b0 = g_bias_c[n], b1 = g_bias_c[n + 1];
#pragma unroll
            for (int half = 0; half < 2; half++) {
                int lr = wm * 32 + mt * 16 + gid + half * 8;
                int row = row0 + lr;
                float c0 = tanh_fast(acc[mt][nt][half * 2]     + b0);
                float c1 = tanh_fast(acc[mt][nt][half * 2 + 1] + b1);
                float z0 = z_s[lr * HR_STR + n];
                float z1 = z_s[lr * HR_STR + n + 1];
                float hr0 = hr_s[lr * HR_STR + n];
                float hr1 = hr_s[lr * HR_STR + n + 1];
                float2 hn = make_float2((1.f - z0) * hr0, (1.f - z1) * hr1);
                size_t idx = (size_t)row * FF + n;
                *reinterpret_cast<float2*>(g_h + idx) = hn;
                float2 ov = *reinterpret_cast<float2*>(g_out + idx);
                ov.x += hn.x + z0 * c0;
                ov.y += hn.y + z1 * c1;
                *reinterpret_cast<float2*>(g_out + idx) = ov;
            }
        }
    }
}

// ---------------- pooling + classifier ----------------
__global__ void k_pool(const float* __restrict__ Wlin, const float* __restrict__ blin,
                       float* __restrict__ y) {
    int g = blockIdx.x;
    int f = threadIdx.x;
    const float* base = g_out + (size_t)g * NPG * FF + f;
    float s = 0.f;
#pragma unroll 4
    for (int n = 0; n < NPG; n++) s += base[(size_t)n * FF];
    s *= (1.0f / (float)NPG);
    float p0 = s * __ldg(Wlin + 2 * f);
    float p1 = s * __ldg(Wlin + 2 * f + 1);
#pragma unroll
    for (int off = 16; off > 0; off >>= 1) {
        p0 += __shfl_down_sync(0xffffffffu, p0, off);
        p1 += __shfl_down_sync(0xffffffffu, p1, off);
    }
    __shared__ float r0s[4], r1s[4];
    int w = f >> 5, lane = f & 31;
    if (lane == 0) { r0s[w] = p0; r1s[w] = p1; }
    __syncthreads();
    if (f == 0) {
        y[2 * g]     = r0s[0] + r0s[1] + r0s[2] + r0s[3] + __ldg(blin);
        y[2 * g + 1] = r1s[0] + r1s[1] + r1s[2] + r1s[3] + __ldg(blin + 1);
    }
}

// ---------------- launch ----------------
extern "C" void kernel_launch(void* const* d_in, const int* in_sizes, int n_in,
                              void* d_out, int out_size) {
    const float* xs = nullptr;
    const float* eas = nullptr;
    const int*   eis = nullptr;
    const float* Wg[6] = {nullptr, nullptr, nullptr, nullptr, nullptr, nullptr};
    const float* bg[6] = {nullptr, nullptr, nullptr, nullptr, nullptr, nullptr};
    const float* Wlin = nullptr;
    const float* blin = nullptr;
    int wi = 0, bi = 0;
    for (int i = 0; i < n_in; i++) {
        long sz = in_sizes[i];
        void* p = d_in[i];
        if (sz == (long)TT * NN * FF)      xs  = (const float*)p;
        else if (sz == (long)TT * EE)      eas = (const float*)p;
        else if (sz == (long)2 * TT * EE)  eis = (const int*)p;
        else if (sz == (long)NN)           { /* batch: contiguous by construction */ }
        else if (sz == (long)FF * FF && wi < 6) Wg[wi++] = (const float*)p;
        else if (sz == (long)FF && bi < 6)      bg[bi++] = (const float*)p;
        else if (sz == (long)FF * CC)      Wlin = (const float*)p;
        else if (sz == (long)CC)           blin = (const float*)p;
    }
    float* y = (float*)d_out;

    const int SMEM_GRU = (BM * AS_STR + KC * BSZ_STR + 2 * BM * HR_STR) * 4;  // 187392 B
    cudaFuncSetAttribute(k_gru, cudaFuncAttributeMaxDynamicSharedMemorySize, SMEM_GRU);

    k_init_hout<<<(NN * FF / 4 + 255) / 256, 256>>>();
    k_pack<<<(65536 + 32768 + 256 + 128 + 255) / 256, 256>>>(
        Wg[0], bg[0], Wg[1], bg[1], Wg[2], bg[2],
        Wg[3], bg[3], Wg[4], bg[4], Wg[5], bg[5]);

    // h-independent pipeline, batched over all 4 timesteps
    k_prep4<<<(TT * NN + 255) / 256, 256>>>();
    k_cnt4<<<dim3((EE + 255) / 256, TT), 256>>>(eis);
    k_scan1<<<dim3(NBLK, TT), 256>>>();
    k_scan2<<<TT, 512>>>();
    k_scan3<<<dim3(NBLK, TT), 256>>>();
    k_fill4<<<dim3((EE + 255) / 256, TT), 256>>>(eas, eis);
    k_deg4<<<(TT * NN + 255) / 256, 256>>>();
    k_agg4<<<dim3((NN * 32 + 255) / 256, TT), 256>>>(xs);

    // sequential GRU steps (h dependency)
    for (int t = 0; t < TT; t++)
        k_gru<<<NN / BM, 512, SMEM_GRU>>>(t);

    k_pool<<<BB, 128>>>(Wlin, blin, y);
}

// round 8
// speedup vs baseline: 5.0329x; 1.2018x over previous
#include <cuda_runtime.h>
#include <cuda_fp16.h>
#include <cstdint>

#define NN 113664
#define FF 128
#define EE 909312
#define TT 4
#define BB 1024
#define CC 2
#define NPG 111        // nodes per graph = NN/BB
#define NBLK 444       // NN / 256

// GEMM tiling (fp16 mma.m16n8k16)
#define BM 128         // rows per CTA
#define KC 32          // K floats per chunk (16 half2)
#define AS_STR 20      // As row stride in uints (16 half2 + pad) -> conflict-free frags
#define BSZ_STR 264    // Bs k2-row stride GEMM1 (n=256)
#define BSC_STR 136    // Bs k2-row stride GEMM2 (n=128)
#define HR_STR 132     // z/hr smem stride (floats)

// ---------------- device scratch (static: no runtime allocation) ----------------
__device__ float g_dinv[TT * NN];
__device__ int   g_cnt [TT * NN];
__device__ int   g_rowptr[TT * (NN + 1)];
__device__ int   g_cursor[TT * NN];
__device__ int   g_bsum[TT * NBLK];
__device__ int   g_boff[TT * (NBLK + 1)];
__device__ int   g_col[TT * EE];
__device__ float g_val[TT * EE];
__device__ float g_ax [TT * NN * FF];
__device__ float g_h  [NN * FF];
__device__ float g_out[NN * FF];
__device__ unsigned g_Wzr[128 * 256];   // half2 packed [k2][n]: k pairs, n<128:z n>=128:r
__device__ unsigned g_Whc[128 * 128];   // half2 packed [k2][n]
__device__ float g_bias_zr[256];
__device__ float g_bias_c[128];

// ---------------- math helpers ----------------
__device__ __forceinline__ float tanh_fast(float x) {
    float y;
    asm("tanh.approx.f32 %0, %1;" : "=f"(y) : "f"(x));
    return y;
}
__device__ __forceinline__ float sigmoid_fast(float x) {
    return 0.5f * tanh_fast(0.5f * x) + 0.5f;
}
__device__ __forceinline__ unsigned pkh2(float a, float b) {
    __half2 h = __float22half2_rn(make_float2(a, b));
    return *reinterpret_cast<unsigned*>(&h);
}
__device__ __forceinline__ void mma_f16(float d[4], const unsigned a[4], const unsigned b[2]) {
    asm volatile(
        "mma.sync.aligned.m16n8k16.row.col.f32.f16.f16.f32 "
        "{%0,%1,%2,%3}, {%4,%5,%6,%7}, {%8,%9}, {%0,%1,%2,%3};"
        : "+f"(d[0]), "+f"(d[1]), "+f"(d[2]), "+f"(d[3])
        : "r"(a[0]), "r"(a[1]), "r"(a[2]), "r"(a[3]), "r"(b[0]), "r"(b[1]));
}

// ---------------- init: h0 = eye(N,F), out = 0 ----------------
__global__ void k_init_hout() {
    int idx = blockIdx.x * blockDim.x + threadIdx.x;
    if (idx >= NN * FF / 4) return;
    float4 z4 = make_float4(0.f, 0.f, 0.f, 0.f);
    reinterpret_cast<float4*>(g_out)[idx] = z4;
    int base = idx * 4;
    int row = base >> 7;
    int col = base & 127;
    float4 h4 = z4;
    if (row < FF && row >= col && row <= col + 3) {
        (&h4.x)[row - col] = 1.0f;
    }
    reinterpret_cast<float4*>(g_h)[idx] = h4;
}

// ---------------- weight packing: half2 [k2][n] + fused biases ----------------
__global__ void k_pack(const float* __restrict__ Wzi, const float* __restrict__ bzi,
                       const float* __restrict__ Wzh, const float* __restrict__ bzh,
                       const float* __restrict__ Wri, const float* __restrict__ bri,
                       const float* __restrict__ Wrh, const float* __restrict__ brh,
                       const float* __restrict__ Whi, const float* __restrict__ bhi,
                       const float* __restrict__ Whh, const float* __restrict__ bhh) {
    int i = blockIdx.x * blockDim.x + threadIdx.x;
    if (i < 32768) {                       // g_Wzr: [k2=0..127][n=0..255]
        int k2 = i >> 8, n = i & 255;
        int k = 2 * k2;
        float v0, v1;
        if (k < 128) {
            v0 = (n < 128) ? Wzi[k * 128 + n]       : Wri[k * 128 + (n - 128)];
            v1 = (n < 128) ? Wzi[(k + 1) * 128 + n] : Wri[(k + 1) * 128 + (n - 128)];
        } else {
            int kk = k - 128;
            v0 = (n < 128) ? Wzh[kk * 128 + n]       : Wrh[kk * 128 + (n - 128)];
            v1 = (n < 128) ? Wzh[(kk + 1) * 128 + n] : Wrh[(kk + 1) * 128 + (n - 128)];
        }
        g_Wzr[i] = pkh2(v0, v1);
    } else if (i < 32768 + 16384) {        // g_Whc: [k2=0..127][n=0..127]
        int j = i - 32768;
        int k2 = j >> 7, n = j & 127;
        int k = 2 * k2;
        float v0, v1;
        if (k < 128) { v0 = Whi[k * 128 + n]; v1 = Whi[(k + 1) * 128 + n]; }
        else { int kk = k - 128; v0 = Whh[kk * 128 + n]; v1 = Whh[(kk + 1) * 128 + n]; }
        g_Whc[j] = pkh2(v0, v1);
    } else if (i < 32768 + 16384 + 256) {
        int n = i - (32768 + 16384);
        g_bias_zr[n] = (n < 128) ? (bzi[n] + bzh[n]) : (bri[n - 128] + brh[n - 128]);
    } else if (i < 32768 + 16384 + 384) {
        int n = i - (32768 + 16384 + 256);
        g_bias_c[n] = bhi[n] + bhh[n];
    }
}

// ---------------- batched per-step CSR build (all TT steps at once) ----------------
__global__ void k_prep4() {
    int i = blockIdx.x * blockDim.x + threadIdx.x;
    if (i < TT * NN) g_cnt[i] = 0;
}

__global__ void k_cnt4(const int* __restrict__ eis) {
    int e = blockIdx.x * blockDim.x + threadIdx.x;
    int t = blockIdx.y;
    if (e >= EE) return;
    int d = eis[(size_t)t * 2 * EE + EE + e];
    atomicAdd(&g_cnt[t * NN + d], 1);
}

__global__ void k_scan1() {
    __shared__ int sh[256];
    int tid = threadIdx.x;
    int t = blockIdx.y;
    sh[tid] = g_cnt[t * NN + blockIdx.x * 256 + tid];
    __syncthreads();
#pragma unroll
    for (int off = 128; off > 0; off >>= 1) {
        if (tid < off) sh[tid] += sh[tid + off];
        __syncthreads();
    }
    if (tid == 0) g_bsum[t * NBLK + blockIdx.x] = sh[0];
}

__global__ void k_scan2() {
    __shared__ int sh[512];
    int tid = threadIdx.x;
    int t = blockIdx.x;
    int v = (tid < NBLK) ? g_bsum[t * NBLK + tid] : 0;
    sh[tid] = v;
    __syncthreads();
#pragma unroll
    for (int off = 1; off < 512; off <<= 1) {
        int u = (tid >= off) ? sh[tid - off] : 0;
        __syncthreads();
        sh[tid] += u;
        __syncthreads();
    }
    if (tid < NBLK) g_boff[t * (NBLK + 1) + tid] = sh[tid] - v;
    if (tid == NBLK - 1) g_boff[t * (NBLK + 1) + NBLK] = sh[tid];
}

__global__ void k_scan3() {
    __shared__ int sh[256];
    int tid = threadIdx.x;
    int t = blockIdx.y;
    int i = blockIdx.x * 256 + tid;
    int c = g_cnt[t * NN + i];
    sh[tid] = c;
    __syncthreads();
#pragma unroll
    for (int off = 1; off < 256; off <<= 1) {
        int u = (tid >= off) ? sh[tid - off] : 0;
        __syncthreads();
        sh[tid] += u;
        __syncthreads();
    }
    int excl = sh[tid] - c + g_boff[t * (NBLK + 1) + blockIdx.x];
    g_rowptr[t * (NN + 1) + i] = excl;
    g_cursor[t * NN + i] = excl;
    if (i == NN - 1) g_rowptr[t * (NN + 1) + NN] = excl + c;
}

__global__ void k_fill4(const float* __restrict__ eas, const int* __restrict__ eis) {
    int e = blockIdx.x * blockDim.x + threadIdx.x;
    int t = blockIdx.y;
    if (e >= EE) return;
    int s = eis[(size_t)t * 2 * EE + e];
    int d = eis[(size_t)t * 2 * EE + EE + e];
    int pos = atomicAdd(&g_cursor[t * NN + d], 1);
    g_col[(size_t)t * EE + pos] = s;
    g_val[(size_t)t * EE + pos] = eas[(size_t)t * EE + e];
}

__global__ void k_deg4() {
    int i = blockIdx.x * blockDim.x + threadIdx.x;
    if (i >= TT * NN) return;
    int t = i / NN;
    int nidx = i - t * NN;
    int beg = g_rowptr[t * (NN + 1) + nidx], end = g_rowptr[t * (NN + 1) + nidx + 1];
    const float* val = g_val + (size_t)t * EE;
    float s = 1.0f;
    for (int j = beg; j < end; j++) s += val[j];
    g_dinv[i] = rsqrtf(s);
}

__global__ void k_agg4(const float* __restrict__ xs) {
    int gw = (blockIdx.x * blockDim.x + threadIdx.x) >> 5;
    int t = blockIdx.y;
    if (gw >= NN) return;
    int lane = threadIdx.x & 31;

    const float* x = xs + (size_t)t * NN * FF;
    float dinv_d = g_dinv[t * NN + gw];
    float self = dinv_d * dinv_d;
    float4 xv = __ldg(reinterpret_cast<const float4*>(x + (size_t)gw * FF) + lane);

    float4 a = make_float4(0.f, 0.f, 0.f, 0.f);
    int beg = g_rowptr[t * (NN + 1) + gw], end = g_rowptr[t * (NN + 1) + gw + 1];
    const int* col = g_col + (size_t)t * EE;
    const float* val = g_val + (size_t)t * EE;
    const float* dinv = g_dinv + t * NN;
    for (int j = beg; j < end; j++) {
        int s = col[j];
        float v = val[j] * dinv[s];
        float4 xsv = __ldg(reinterpret_cast<const float4*>(x + (size_t)s * FF) + lane);
        a.x += v * xsv.x; a.y += v * xsv.y; a.z += v * xsv.z; a.w += v * xsv.w;
    }
    a.x = dinv_d * a.x + self * xv.x;
    a.y = dinv_d * a.y + self * xv.y;
    a.z = dinv_d * a.z + self * xv.z;
    a.w = dinv_d * a.w + self * xv.w;
    reinterpret_cast<float4*>(g_ax + (size_t)t * NN * FF + (size_t)gw * FF)[lane] = a;
}

// ================= Fused GRU step (fp16 mma, register-prefetch), BM=128, 512 thr =================
// 16 warps as 4x4: wm in {0..3} (32-row groups), wn in {0..3}.
// GEMM1: [ax|h](128x256) @ Wzr(256x256) -> z (smem), hr (smem; raw h cached during staging)
// GEMM2: [ax|hr](128x256) @ Whc(256x128) -> cand; epilogue updates g_h, g_out.
__global__ void __launch_bounds__(512, 1) k_gru(int step) {
    extern __shared__ unsigned sm[];
    unsigned* As = sm;                                   // [128][AS_STR] half2
    unsigned* Bs = sm + BM * AS_STR;                     // [16][BSZ_STR] half2
    float* hr_s = reinterpret_cast<float*>(sm + BM * AS_STR + 16 * BSZ_STR); // [128][HR_STR]
    float* z_s  = hr_s + BM * HR_STR;                    // [128][HR_STR]

    const float* ax = g_ax + (size_t)step * NN * FF;
    const int tid = threadIdx.x;
    const int w = tid >> 5, lane = tid & 31;
    const int wm = w & 3, wn = w >> 2;
    const int gid = lane >> 2, tig = lane & 3;
    const int row0 = blockIdx.x * BM;
    const int ar = tid >> 2, aq = tid & 3;   // A staging: row ar, 8-float group aq

    // ---------------- GEMM1: N=256 ----------------
    {
        float acc[2][8][4];
#pragma unroll
        for (int mt = 0; mt < 2; mt++)
#pragma unroll
            for (int nt = 0; nt < 8; nt++)
#pragma unroll
                for (int q = 0; q < 4; q++) acc[mt][nt][q] = 0.f;

        // prologue: load chunk 0 into regs
        float4 av0, av1;
        uint4 bv0, bv1;
        {
            const float4* Ap = reinterpret_cast<const float4*>(ax + (size_t)(row0 + ar) * FF);
            av0 = __ldg(Ap + aq * 2);
            av1 = __ldg(Ap + aq * 2 + 1);
            const uint4* Bp = reinterpret_cast<const uint4*>(g_Wzr);
            bv0 = Bp[tid]; bv1 = Bp[tid + 512];
        }

#pragma unroll
        for (int chunk = 0; chunk < 8; chunk++) {
            // store staged regs -> smem
            {
                uint4 pk = make_uint4(pkh2(av0.x, av0.y), pkh2(av0.z, av0.w),
                                      pkh2(av1.x, av1.y), pkh2(av1.z, av1.w));
                *reinterpret_cast<uint4*>(As + ar * AS_STR + aq * 4) = pk;
                if (chunk >= 4) {     // cache raw h for epilogue1
                    float* hd = hr_s + ar * HR_STR + (chunk & 3) * KC + aq * 8;
                    *reinterpret_cast<float4*>(hd) = av0;
                    *reinterpret_cast<float4*>(hd + 4) = av1;
                }
                int i0 = tid;
                *reinterpret_cast<uint4*>(Bs + (i0 >> 6) * BSZ_STR + (i0 & 63) * 4) = bv0;
                int i1 = tid + 512;
                *reinterpret_cast<uint4*>(Bs + (i1 >> 6) * BSZ_STR + (i1 & 63) * 4) = bv1;
            }
            __syncthreads();

            // prefetch next chunk (LDGs overlap the MMA loop below)
            if (chunk < 7) {
                int nc = chunk + 1;
                const float* Abase = ((nc < 4) ? ax : g_h) + (size_t)(row0 + ar) * FF + (nc & 3) * KC;
                av0 = __ldg(reinterpret_cast<const float4*>(Abase) + aq * 2);
                av1 = __ldg(reinterpret_cast<const float4*>(Abase) + aq * 2 + 1);
                const uint4* Bp = reinterpret_cast<const uint4*>(g_Wzr + (size_t)nc * 4096);
                bv0 = Bp[tid]; bv1 = Bp[tid + 512];
            }

#pragma unroll
            for (int ks = 0; ks < 2; ks++) {
                int kb = ks * 8;
                unsigned a[2][4];
#pragma unroll
                for (int mt = 0; mt < 2; mt++) {
                    int rb = wm * 32 + mt * 16 + gid;
                    a[mt][0] = As[rb * AS_STR + kb + tig];
                    a[mt][1] = As[(rb + 8) * AS_STR + kb + tig];
                    a[mt][2] = As[rb * AS_STR + kb + tig + 4];
                    a[mt][3] = As[(rb + 8) * AS_STR + kb + tig + 4];
                }
#pragma unroll
                for (int nt = 0; nt < 8; nt++) {
                    unsigned b[2];
                    int cb = wn * 64 + nt * 8 + gid;
                    b[0] = Bs[(kb + tig) * BSZ_STR + cb];
                    b[1] = Bs[(kb + tig + 4) * BSZ_STR + cb];
                    mma_f16(acc[0][nt], a[0], b);
                    mma_f16(acc[1][nt], a[1], b);
                }
            }
            __syncthreads();
        }

        // epilogue1: wn 0,1 -> z cols [0,128) to z_s; wn 2,3 -> hr = sig(.)*h (h cached in hr_s)
#pragma unroll
        for (int mt = 0; mt < 2; mt++) {
#pragma unroll
            for (int nt = 0; nt < 8; nt++) {
                int col = wn * 64 + nt * 8 + 2 * tig;
                int lr1 = wm * 32 + mt * 16 + gid;
                int lr2 = lr1 + 8;
                float b0 = g_bias_zr[col], b1 = g_bias_zr[col + 1];
                if (wn < 2) {
                    int n = col;
                    z_s[lr1 * HR_STR + n]     = sigmoid_fast(acc[mt][nt][0] + b0);
                    z_s[lr1 * HR_STR + n + 1] = sigmoid_fast(acc[mt][nt][1] + b1);
                    z_s[lr2 * HR_STR + n]     = sigmoid_fast(acc[mt][nt][2] + b0);
                    z_s[lr2 * HR_STR + n + 1] = sigmoid_fast(acc[mt][nt][3] + b1);
                } else {
                    int n = col - 128;
                    float h10 = hr_s[lr1 * HR_STR + n],  h11 = hr_s[lr1 * HR_STR + n + 1];
                    float h20 = hr_s[lr2 * HR_STR + n],  h21 = hr_s[lr2 * HR_STR + n + 1];
                    hr_s[lr1 * HR_STR + n]     = sigmoid_fast(acc[mt][nt][0] + b0) * h10;
                    hr_s[lr1 * HR_STR + n + 1] = sigmoid_fast(acc[mt][nt][1] + b1) * h11;
                    hr_s[lr2 * HR_STR + n]     = sigmoid_fast(acc[mt][nt][2] + b0) * h20;
                    hr_s[lr2 * HR_STR + n + 1] = sigmoid_fast(acc[mt][nt][3] + b1) * h21;
                }
            }
        }
    }
    __syncthreads();   // z_s / hr_s visible to all warps

    // ---------------- GEMM2: N=128, A = [ax | hr_s] ----------------
    float acc[2][4][4];
#pragma unroll
    for (int mt = 0; mt < 2; mt++)
#pragma unroll
        for (int nt = 0; nt < 4; nt++)
#pragma unroll
            for (int q = 0; q < 4; q++) acc[mt][nt][q] = 0.f;

    float4 av0, av1;
    uint4 bv0;
    {
        const float4* Ap = reinterpret_cast<const float4*>(ax + (size_t)(row0 + ar) * FF);
        av0 = __ldg(Ap + aq * 2);
        av1 = __ldg(Ap + aq * 2 + 1);
        bv0 = reinterpret_cast<const uint4*>(g_Whc)[tid];
    }

#pragma unroll
    for (int chunk = 0; chunk < 8; chunk++) {
        if (chunk < 4) {
            uint4 pk = make_uint4(pkh2(av0.x, av0.y), pkh2(av0.z, av0.w),
                                  pkh2(av1.x, av1.y), pkh2(av1.z, av1.w));
            *reinterpret_cast<uint4*>(As + ar * AS_STR + aq * 4) = pk;
        }
        *reinterpret_cast<uint4*>(Bs + (tid >> 5) * BSC_STR + (tid & 31) * 4) = bv0;
        __syncthreads();

        if (chunk < 7) {
            int nc = chunk + 1;
            bv0 = reinterpret_cast<const uint4*>(g_Whc + (size_t)nc * 2048)[tid];
            if (nc < 4) {
                const float* Abase = ax + (size_t)(row0 + ar) * FF + nc * KC;
                av0 = __ldg(reinterpret_cast<const float4*>(Abase) + aq * 2);
                av1 = __ldg(reinterpret_cast<const float4*>(Abase) + aq * 2 + 1);
            }
        }

#pragma unroll
        for (int ks = 0; ks < 2; ks++) {
            int kb = ks * 8;
            unsigned a[2][4];
#pragma unroll
            for (int mt = 0; mt < 2; mt++) {
                int rb = wm * 32 + mt * 16 + gid;
                if (chunk < 4) {
                    a[mt][0] = As[rb * AS_STR + kb + tig];
                    a[mt][1] = As[(rb + 8) * AS_STR + kb + tig];
                    a[mt][2] = As[rb * AS_STR + kb + tig + 4];
                    a[mt][3] = As[(rb + 8) * AS_STR + kb + tig + 4];
                } else {
                    int kf = (chunk - 4) * KC + ks * 16 + 2 * tig;
                    float2 v0 = *reinterpret_cast<const float2*>(hr_s + rb * HR_STR + kf);
                    float2 v1 = *reinterpret_cast<const float2*>(hr_s + (rb + 8) * HR_STR + kf);
                    float2 v2 = *reinterpret_cast<const float2*>(hr_s + rb * HR_STR + kf + 8);
                    float2 v3 = *reinterpret_cast<const float2*>(hr_s + (rb + 8) * HR_STR + kf + 8);
                    a[mt][0] = pkh2(v0.x, v0.y);
                    a[mt][1] = pkh2(v1.x, v1.y);
                    a[mt][2] = pkh2(v2.x, v2.y);
                    a[mt][3] = pkh2(v3.x, v3.y);
                }
            }
#pragma unroll
            for (int nt = 0; nt < 4; nt++) {
                unsigned b[2];
                int cb = wn * 32 + nt * 8 + gid;
                b[0] = Bs[(kb + tig) * BSC_STR + cb];
                b[1] = Bs[(kb + tig + 4) * BSC_STR + cb];
                mma_f16(acc[0][nt], a[0], b);
                mma_f16(acc[1][nt], a[1], b);
            }
        }
        __syncthreads();
    }

    // epilogue2: cand = tanh(acc + bias); hn = (1-z)*hr; h = hn; out += hn + z*cand
#pragma unroll
    for (int mt = 0; mt < 2; mt++) {
#pragma unroll
        for (int nt = 0; nt < 4; nt++) {
            int n = wn * 32 + nt * 8 + 2 * tig;
            float b0 = g_bias_c[n], b1 = g_bias_c[n + 1];
#pragma unroll
            for (int half = 0; half < 2; half++) {
                int lr = wm * 32 + mt * 16 + gid + half * 8;
                int row = row0 + lr;
                float c0 = tanh_fast(acc[mt][nt][half * 2]     + b0);
                float c1 = tanh_fast(acc[mt][nt][half * 2 + 1] + b1);
                float z0 = z_s[lr * HR_STR + n];
                float z1 = z_s[lr * HR_STR + n + 1];
                float hr0 = hr_s[lr * HR_STR + n];
                float hr1 = hr_s[lr * HR_STR + n + 1];
                float2 hn = make_float2((1.f - z0) * hr0, (1.f - z1) * hr1);
                size_t idx = (size_t)row * FF + n;
                *reinterpret_cast<float2*>(g_h + idx) = hn;
                float2 ov = *reinterpret_cast<float2*>(g_out + idx);
                ov.x += hn.x + z0 * c0;
                ov.y += hn.y + z1 * c1;
                *reinterpret_cast<float2*>(g_out + idx) = ov;
            }
        }
    }
}

// ---------------- pooling + classifier ----------------
__global__ void k_pool(const float* __restrict__ Wlin, const float* __restrict__ blin,
                       float* __restrict__ y) {
    int g = blockIdx.x;
    int f = threadIdx.x;
    const float* base = g_out + (size_t)g * NPG * FF + f;
    float s = 0.f;
#pragma unroll 4
    for (int n = 0; n < NPG; n++) s += base[(size_t)n * FF];
    s *= (1.0f / (float)NPG);
    float p0 = s * __ldg(Wlin + 2 * f);
    float p1 = s * __ldg(Wlin + 2 * f + 1);
#pragma unroll
    for (int off = 16; off > 0; off >>= 1) {
        p0 += __shfl_down_sync(0xffffffffu, p0, off);
        p1 += __shfl_down_sync(0xffffffffu, p1, off);
    }
    __shared__ float r0s[4], r1s[4];
    int w = f >> 5, lane = f & 31;
    if (lane == 0) { r0s[w] = p0; r1s[w] = p1; }
    __syncthreads();
    if (f == 0) {
        y[2 * g]     = r0s[0] + r0s[1] + r0s[2] + r0s[3] + __ldg(blin);
        y[2 * g + 1] = r1s[0] + r1s[1] + r1s[2] + r1s[3] + __ldg(blin + 1);
    }
}

// ---------------- launch ----------------
extern "C" void kernel_launch(void* const* d_in, const int* in_sizes, int n_in,
                              void* d_out, int out_size) {
    const float* xs = nullptr;
    const float* eas = nullptr;
    const int*   eis = nullptr;
    const float* Wg[6] = {nullptr, nullptr, nullptr, nullptr, nullptr, nullptr};
    const float* bg[6] = {nullptr, nullptr, nullptr, nullptr, nullptr, nullptr};
    const float* Wlin = nullptr;
    const float* blin = nullptr;
    int wi = 0, bi = 0;
    for (int i = 0; i < n_in; i++) {
        long sz = in_sizes[i];
        void* p = d_in[i];
        if (sz == (long)TT * NN * FF)      xs  = (const float*)p;
        else if (sz == (long)TT * EE)      eas = (const float*)p;
        else if (sz == (long)2 * TT * EE)  eis = (const int*)p;
        else if (sz == (long)NN)           { /* batch: contiguous by construction */ }
        else if (sz == (long)FF * FF && wi < 6) Wg[wi++] = (const float*)p;
        else if (sz == (long)FF && bi < 6)      bg[bi++] = (const float*)p;
        else if (sz == (long)FF * CC)      Wlin = (const float*)p;
        else if (sz == (long)CC)           blin = (const float*)p;
    }
    float* y = (float*)d_out;

    const int SMEM_GRU = (BM * AS_STR + 16 * BSZ_STR + 2 * BM * HR_STR) * 4;  // 162304 B
    cudaFuncSetAttribute(k_gru, cudaFuncAttributeMaxDynamicSharedMemorySize, SMEM_GRU);

    k_init_hout<<<(NN * FF / 4 + 255) / 256, 256>>>();
    k_pack<<<(32768 + 16384 + 384 + 255) / 256, 256>>>(
        Wg[0], bg[0], Wg[1], bg[1], Wg[2], bg[2],
        Wg[3], bg[3], Wg[4], bg[4], Wg[5], bg[5]);

    // h-independent pipeline, batched over all 4 timesteps
    k_prep4<<<(TT * NN + 255) / 256, 256>>>();
    k_cnt4<<<dim3((EE + 255) / 256, TT), 256>>>(eis);
    k_scan1<<<dim3(NBLK, TT), 256>>>();
    k_scan2<<<TT, 512>>>();
    k_scan3<<<dim3(NBLK, TT), 256>>>();
    k_fill4<<<dim3((EE + 255) / 256, TT), 256>>>(eas, eis);
    k_deg4<<<(TT * NN + 255) / 256, 256>>>();
    k_agg4<<<dim3((NN * 32 + 255) / 256, TT), 256>>>(xs);

    // sequential GRU steps (h dependency)
    for (int t = 0; t < TT; t++)
        k_gru<<<NN / BM, 512, SMEM_GRU>>>(t);

    k_pool<<<BB, 128>>>(Wlin, blin, y);
}